// round 2
// baseline (speedup 1.0000x reference)
#include <cuda_runtime.h>
#include <math.h>

// Problem constants
#define BWIN   4096
#define NTOK   49
#define DIMC   192
#define HEADS  6
#define HDIM   32
#define NWMASK 64
#define QSCALE 0.17677669529663687f   // 32^-0.5

// Shared-memory layout (in floats) — all region bases multiple of 4 floats (16B)
#define XS_STRIDE  193                 // 49 x 193 padded x tile (scalar access only)
#define QKV_STRIDE 196                 // 49 x 196 padded q/k/v (and O) tiles
#define ATT_STRIDE 56                  // 6 x 49 x 56 attention matrix

#define OFF_XS   0
#define OFF_WP   9460                  // 49*193=9457 rounded up to 16B alignment
#define OFF_B    18676                 // OFF_WP + 16*576
#define SMEM_FLOATS (18676 + 3 * 49 * 196)   // 47488 floats = 189,952 B

// ---- packed f32x2 helpers (full-rate fp32 on sm_103a) ----
__device__ __forceinline__ unsigned long long pack2(float lo, float hi) {
    unsigned long long r;
    asm("mov.b64 %0, {%1, %2};" : "=l"(r) : "f"(lo), "f"(hi));
    return r;
}
__device__ __forceinline__ unsigned long long fma2(unsigned long long a,
                                                   unsigned long long b,
                                                   unsigned long long c) {
    unsigned long long d;
    asm("fma.rn.f32x2 %0, %1, %2, %3;" : "=l"(d) : "l"(a), "l"(b), "l"(c));
    return d;
}
__device__ __forceinline__ void unpack2(unsigned long long v, float& lo, float& hi) {
    asm("mov.b64 {%0, %1}, %2;" : "=f"(lo), "=f"(hi) : "l"(v));
}

__global__ __launch_bounds__(256, 1)
void winattn_fused_kernel(const float* __restrict__ x,
                          const float* __restrict__ mask,
                          const float* __restrict__ w_qkv,
                          const float* __restrict__ b_qkv,
                          const float* __restrict__ w_proj,
                          const float* __restrict__ b_proj,
                          const float* __restrict__ table,
                          float* __restrict__ out)
{
    extern __shared__ float sm[];
    float* xs  = sm + OFF_XS;      // 49 x 193   (phase 1)
    float* wp  = sm + OFF_WP;      // 16 x 576   (phase 1) / 16 x 192 (phase 3)
    float* att = sm + OFF_XS;      // 6 x 49 x 56 (phase 2, overlays xs+wp)
    float* qs  = sm + OFF_B;       // 49 x 196   (later becomes O)
    float* ks  = qs + NTOK * QKV_STRIDE;
    float* vs  = ks + NTOK * QKV_STRIDE;

    const int tid = threadIdx.x;
    const int b   = blockIdx.x;
    const float* xg = x + (size_t)b * (NTOK * DIMC);

    // ---------------- load x window into smem ----------------
    for (int i = tid; i < NTOK * DIMC; i += 256) {
        xs[(i / DIMC) * XS_STRIDE + (i % DIMC)] = xg[i];
    }

    // ---------------- phase 1: qkv = x @ w_qkv + b_qkv ----------------
    // 252 active threads: rg = row-group (7 rows), cgbase -> 16 cols (4 groups of 4, stride 144)
    const int rg     = tid / 36;       // 0..6 for tid<252
    const int cgbase = tid % 36;
    const bool p1act = (tid < 252);

    unsigned long long acc[7][8];
    #pragma unroll
    for (int i = 0; i < 7; i++)
        #pragma unroll
        for (int j = 0; j < 8; j++) acc[i][j] = 0ULL;

    for (int kp = 0; kp < 12; ++kp) {
        __syncthreads();
        {   // stage 16x576 panel of w_qkv
            const float4* wsrc = (const float4*)(w_qkv + kp * 16 * 576);
            float4* wdst = (float4*)wp;
            for (int i = tid; i < 2304; i += 256) wdst[i] = wsrc[i];
        }
        __syncthreads();
        if (p1act) {
            #pragma unroll
            for (int kk = 0; kk < 16; ++kk) {
                unsigned long long xv2[7];
                #pragma unroll
                for (int i = 0; i < 7; i++) {
                    float xv = xs[(rg * 7 + i) * XS_STRIDE + kp * 16 + kk];
                    xv2[i] = pack2(xv, xv);
                }
                #pragma unroll
                for (int g = 0; g < 4; ++g) {
                    float4 wv = *(const float4*)&wp[kk * 576 + (cgbase + 36 * g) * 4];
                    unsigned long long w01 = pack2(wv.x, wv.y);
                    unsigned long long w23 = pack2(wv.z, wv.w);
                    #pragma unroll
                    for (int i = 0; i < 7; i++) {
                        acc[i][2 * g]     = fma2(xv2[i], w01, acc[i][2 * g]);
                        acc[i][2 * g + 1] = fma2(xv2[i], w23, acc[i][2 * g + 1]);
                    }
                }
            }
        }
    }

    // write q (scaled), k, v into smem
    if (p1act) {
        #pragma unroll
        for (int g = 0; g < 4; ++g) {
            int cbase = (cgbase + 36 * g) * 4;
            int part  = cbase / DIMC;        // 0=q 1=k 2=v
            int cc    = cbase % DIMC;
            float* dst = (part == 0) ? qs : (part == 1) ? ks : vs;
            float sc   = (part == 0) ? QSCALE : 1.0f;
            float4 bq  = *(const float4*)&b_qkv[cbase];
            #pragma unroll
            for (int i = 0; i < 7; i++) {
                float a0, a1, a2, a3;
                unpack2(acc[i][2 * g], a0, a1);
                unpack2(acc[i][2 * g + 1], a2, a3);
                float4 o;
                o.x = (a0 + bq.x) * sc;
                o.y = (a1 + bq.y) * sc;
                o.z = (a2 + bq.z) * sc;
                o.w = (a3 + bq.w) * sc;
                *(float4*)&dst[(rg * 7 + i) * QKV_STRIDE + cc] = o;
            }
        }
    }
    __syncthreads();

    // ---------------- phase 2a: S = q k^T + bias + mask ----------------
    const float* mrow = mask + (size_t)(b & (NWMASK - 1)) * (NTOK * NTOK);
    for (int t = tid; t < 1014; t += 256) {      // 6 heads x 13 x 13 tiles of 4x4
        int h   = t / 169;
        int rem = t % 169;
        int pg  = rem / 13, qg = rem % 13;
        float a[4][4];
        #pragma unroll
        for (int i = 0; i < 4; i++)
            #pragma unroll
            for (int j = 0; j < 4; j++) a[i][j] = 0.0f;

        int pbase[4], qbase[4];
        #pragma unroll
        for (int i = 0; i < 4; i++) {
            int p = pg * 4 + i; if (p > 48) p = 48;
            pbase[i] = p * QKV_STRIDE + h * HDIM;
        }
        #pragma unroll
        for (int j = 0; j < 4; j++) {
            int q = qg * 4 + j; if (q > 48) q = 48;
            qbase[j] = q * QKV_STRIDE + h * HDIM;
        }
        #pragma unroll
        for (int dd = 0; dd < 8; ++dd) {
            float4 qv[4], kv[4];
            #pragma unroll
            for (int i = 0; i < 4; i++) qv[i] = *(const float4*)&qs[pbase[i] + dd * 4];
            #pragma unroll
            for (int j = 0; j < 4; j++) kv[j] = *(const float4*)&ks[qbase[j] + dd * 4];
            #pragma unroll
            for (int i = 0; i < 4; i++)
                #pragma unroll
                for (int j = 0; j < 4; j++) {
                    a[i][j] = fmaf(qv[i].x, kv[j].x, a[i][j]);
                    a[i][j] = fmaf(qv[i].y, kv[j].y, a[i][j]);
                    a[i][j] = fmaf(qv[i].z, kv[j].z, a[i][j]);
                    a[i][j] = fmaf(qv[i].w, kv[j].w, a[i][j]);
                }
        }
        #pragma unroll
        for (int i = 0; i < 4; i++) {
            int p = pg * 4 + i;
            if (p < NTOK) {
                int ip = p / 7, jp = p % 7;
                #pragma unroll
                for (int j = 0; j < 4; j++) {
                    int q = qg * 4 + j;
                    if (q < NTOK) {
                        int iq = q / 7, jq = q % 7;
                        int ridx = (jp - jq + 6) * 13 + (ip - iq + 6);
                        att[(h * NTOK + p) * ATT_STRIDE + q] =
                            a[i][j] + table[ridx * HEADS + h] + mrow[p * NTOK + q];
                    }
                }
            }
        }
    }
    __syncthreads();

    // ---------------- phase 2b: softmax rows ----------------
    for (int t = tid; t < HEADS * NTOK; t += 256) {
        float* row = att + t * ATT_STRIDE;   // t == h*49 + p
        float m = row[0];
        for (int q = 1; q < NTOK; q++) m = fmaxf(m, row[q]);
        float s = 0.0f;
        for (int q = 0; q < NTOK; q++) {
            float e = __expf(row[q] - m);
            row[q] = e;
            s += e;
        }
        float inv = 1.0f / s;
        for (int q = 0; q < NTOK; q++) row[q] *= inv;
    }
    __syncthreads();

    // ---------------- phase 2c: O = S @ V (O overwrites qs) ----------------
    float* os = qs;
    for (int t = tid; t < 312; t += 256) {   // 6 heads x 13 pgroups x 4 dgroups(8)
        int h   = t / 52;
        int rem = t % 52;
        int pg  = rem / 4, dg = rem % 4;
        float4 a0[4], a1[4];
        #pragma unroll
        for (int i = 0; i < 4; i++) {
            a0[i] = make_float4(0.f, 0.f, 0.f, 0.f);
            a1[i] = make_float4(0.f, 0.f, 0.f, 0.f);
        }
        int pr[4];
        #pragma unroll
        for (int i = 0; i < 4; i++) {
            int p = pg * 4 + i; if (p > 48) p = 48;
            pr[i] = p;
        }
        for (int q = 0; q < NTOK; q++) {
            float4 v0 = *(const float4*)&vs[q * QKV_STRIDE + h * HDIM + dg * 8];
            float4 v1 = *(const float4*)&vs[q * QKV_STRIDE + h * HDIM + dg * 8 + 4];
            #pragma unroll
            for (int i = 0; i < 4; i++) {
                float sv = att[(h * NTOK + pr[i]) * ATT_STRIDE + q];
                a0[i].x = fmaf(sv, v0.x, a0[i].x);
                a0[i].y = fmaf(sv, v0.y, a0[i].y);
                a0[i].z = fmaf(sv, v0.z, a0[i].z);
                a0[i].w = fmaf(sv, v0.w, a0[i].w);
                a1[i].x = fmaf(sv, v1.x, a1[i].x);
                a1[i].y = fmaf(sv, v1.y, a1[i].y);
                a1[i].z = fmaf(sv, v1.z, a1[i].z);
                a1[i].w = fmaf(sv, v1.w, a1[i].w);
            }
        }
        #pragma unroll
        for (int i = 0; i < 4; i++) {
            int p = pg * 4 + i;
            if (p < NTOK) {
                *(float4*)&os[p * QKV_STRIDE + h * HDIM + dg * 8]     = a0[i];
                *(float4*)&os[p * QKV_STRIDE + h * HDIM + dg * 8 + 4] = a1[i];
            }
        }
    }

    // ---------------- phase 3: out = O @ w_proj + b_proj ----------------
    // 336 tiles of 7 rows x 4 cols: t0 = tid (all), t1 = tid+256 (tid<80)
    const int t1v   = tid + 256;
    const bool has1 = (t1v < 336);
    const int rg0 = tid / 48, cg0 = tid % 48;
    const int rg1 = t1v / 48, cg1 = t1v % 48;

    unsigned long long pacc[2][7][2];
    #pragma unroll
    for (int w = 0; w < 2; w++)
        #pragma unroll
        for (int i = 0; i < 7; i++) { pacc[w][i][0] = 0ULL; pacc[w][i][1] = 0ULL; }

    for (int kp = 0; kp < 12; ++kp) {
        __syncthreads();   // also separates phase-2c att reads from wp overwrite
        {
            const float4* wsrc = (const float4*)(w_proj + kp * 16 * DIMC);
            float4* wdst = (float4*)wp;
            for (int i = tid; i < 768; i += 256) wdst[i] = wsrc[i];
        }
        __syncthreads();
        #pragma unroll 4
        for (int kk = 0; kk < 16; ++kk) {
            int k = kp * 16 + kk;
            {
                float4 wv = *(const float4*)&wp[kk * DIMC + cg0 * 4];
                unsigned long long w01 = pack2(wv.x, wv.y);
                unsigned long long w23 = pack2(wv.z, wv.w);
                #pragma unroll
                for (int i = 0; i < 7; i++) {
                    float xv = os[(rg0 * 7 + i) * QKV_STRIDE + k];
                    unsigned long long x2 = pack2(xv, xv);
                    pacc[0][i][0] = fma2(x2, w01, pacc[0][i][0]);
                    pacc[0][i][1] = fma2(x2, w23, pacc[0][i][1]);
                }
            }
            if (has1) {
                float4 wv = *(const float4*)&wp[kk * DIMC + cg1 * 4];
                unsigned long long w01 = pack2(wv.x, wv.y);
                unsigned long long w23 = pack2(wv.z, wv.w);
                #pragma unroll
                for (int i = 0; i < 7; i++) {
                    float xv = os[(rg1 * 7 + i) * QKV_STRIDE + k];
                    unsigned long long x2 = pack2(xv, xv);
                    pacc[1][i][0] = fma2(x2, w01, pacc[1][i][0]);
                    pacc[1][i][1] = fma2(x2, w23, pacc[1][i][1]);
                }
            }
        }
    }

    float* og = out + (size_t)b * (NTOK * DIMC);
    {
        float4 bp = *(const float4*)&b_proj[cg0 * 4];
        #pragma unroll
        for (int i = 0; i < 7; i++) {
            float a0v, a1v, a2v, a3v;
            unpack2(pacc[0][i][0], a0v, a1v);
            unpack2(pacc[0][i][1], a2v, a3v);
            float4 o;
            o.x = a0v + bp.x; o.y = a1v + bp.y; o.z = a2v + bp.z; o.w = a3v + bp.w;
            *(float4*)&og[(rg0 * 7 + i) * DIMC + cg0 * 4] = o;
        }
    }
    if (has1) {
        float4 bp = *(const float4*)&b_proj[cg1 * 4];
        #pragma unroll
        for (int i = 0; i < 7; i++) {
            float a0v, a1v, a2v, a3v;
            unpack2(pacc[1][i][0], a0v, a1v);
            unpack2(pacc[1][i][1], a2v, a3v);
            float4 o;
            o.x = a0v + bp.x; o.y = a1v + bp.y; o.z = a2v + bp.z; o.w = a3v + bp.w;
            *(float4*)&og[(rg1 * 7 + i) * DIMC + cg1 * 4] = o;
        }
    }
}

extern "C" void kernel_launch(void* const* d_in, const int* in_sizes, int n_in,
                              void* d_out, int out_size)
{
    const float* x      = (const float*)d_in[0];
    const float* mask   = (const float*)d_in[1];
    const float* w_qkv  = (const float*)d_in[2];
    const float* b_qkv  = (const float*)d_in[3];
    const float* w_proj = (const float*)d_in[4];
    const float* b_proj = (const float*)d_in[5];
    const float* table  = (const float*)d_in[6];
    float* out = (float*)d_out;

    const int smem_bytes = SMEM_FLOATS * (int)sizeof(float);
    cudaFuncSetAttribute(winattn_fused_kernel,
                         cudaFuncAttributeMaxDynamicSharedMemorySize, smem_bytes);

    winattn_fused_kernel<<<BWIN, 256, smem_bytes>>>(
        x, mask, w_qkv, b_qkv, w_proj, b_proj, table, out);
}

// round 3
// speedup vs baseline: 1.3280x; 1.3280x over previous
#include <cuda_runtime.h>
#include <math.h>

#define BWIN   4096
#define NTOK   49
#define DIMC   192
#define HEADS  6
#define HDIM   32
#define NWMASK 64
#define QSCALE 0.17677669529663687f
#define NTHREADS 512

// smem layout (floats). Strides chosen for conflict-free MMA fragment LDS:
//  xs/qkv stride 196 (%32==4): A-frag bank = 4*(l/4)+(l%4) -> 32 distinct
//  wp1 stride 584, wp3 stride 200 (%32==8): B-frag bank = 8*(l%4)+(l/4) -> 32 distinct
#define XS_STRIDE  196
#define QKV_STRIDE 196
#define ATT_STRIDE 56
#define WP1_STRIDE 584
#define WP3_STRIDE 200

#define OFF_XS 0
#define OFF_WP 9604                       // 49*196
#define OFF_B  18948                      // OFF_WP + 16*584
#define SMEM_FLOATS (18948 + 3 * 9604)    // 47760 floats = 191,040 B

__device__ __forceinline__ unsigned cvt_tf32(float f) {
    unsigned r;
    asm("cvt.rna.tf32.f32 %0, %1;" : "=r"(r) : "f"(f));
    return r;
}

__device__ __forceinline__ void mma_tf32(float* d, const unsigned* a, const unsigned* bb) {
    asm volatile(
        "mma.sync.aligned.m16n8k8.row.col.f32.tf32.tf32.f32 "
        "{%0,%1,%2,%3}, {%4,%5,%6,%7}, {%8,%9}, {%0,%1,%2,%3};"
        : "+f"(d[0]), "+f"(d[1]), "+f"(d[2]), "+f"(d[3])
        : "r"(a[0]), "r"(a[1]), "r"(a[2]), "r"(a[3]),
          "r"(bb[0]), "r"(bb[1]));
}

__global__ __launch_bounds__(NTHREADS, 1)
void winattn_fused_kernel(const float* __restrict__ x,
                          const float* __restrict__ mask,
                          const float* __restrict__ w_qkv,
                          const float* __restrict__ b_qkv,
                          const float* __restrict__ w_proj,
                          const float* __restrict__ b_proj,
                          const float* __restrict__ table,
                          float* __restrict__ out)
{
    extern __shared__ float sm[];
    float* xs  = sm + OFF_XS;            // 49 x 196 (phase 1)
    float* wp  = sm + OFF_WP;            // 16 x 584 (p1) / 16 x 200 (p3)
    float* att = sm + OFF_XS;            // 6 x 49 x 56 (phase 2 overlay, 16464 < 18948)
    float* qs  = sm + OFF_B;             // 49 x 196 (later O)
    float* ks  = qs + NTOK * QKV_STRIDE;
    float* vs  = ks + NTOK * QKV_STRIDE;

    const int tid  = threadIdx.x;
    const int lane = tid & 31;
    const int w    = tid >> 5;
    const int lg   = lane >> 2;          // 0..7
    const int lr   = lane & 3;           // 0..3
    const int b    = blockIdx.x;
    const float* xg = x + (size_t)b * (NTOK * DIMC);

    // ---------------- load x window ----------------
    for (int i = tid; i < NTOK * DIMC; i += NTHREADS)
        xs[(i / DIMC) * XS_STRIDE + (i % DIMC)] = xg[i];

    // ================ phase 1: qkv = x @ w_qkv + b_qkv (TF32 MMA) ================
    // warp -> 72-col N-slice (w>>1), 32-row M-half (w&1). M padded to 64 (predicated A).
    {
        const int n0 = (w >> 1) * 72;
        const int m0 = (w & 1) * 32;
        float d[2][9][4];
        #pragma unroll
        for (int s = 0; s < 2; s++)
            #pragma unroll
            for (int t = 0; t < 9; t++)
                #pragma unroll
                for (int j = 0; j < 4; j++) d[s][t][j] = 0.0f;

        for (int kp = 0; kp < 12; ++kp) {
            __syncthreads();
            // stage 16x576 weight panel, stride 584
            for (int i = tid; i < 16 * 144; i += NTHREADS) {
                int r = i / 144, c4 = i % 144;
                *(float4*)&wp[r * WP1_STRIDE + c4 * 4] =
                    ((const float4*)w_qkv)[(kp * 16 + r) * 144 + c4];
            }
            __syncthreads();
            #pragma unroll
            for (int k8 = 0; k8 < 2; ++k8) {
                const int kb = k8 * 8;
                const int xc = kp * 16 + kb + lr;
                unsigned a[2][4];
                #pragma unroll
                for (int s = 0; s < 2; s++) {
                    int r0 = m0 + s * 16 + lg, r1 = r0 + 8;
                    a[s][0] = cvt_tf32(r0 < NTOK ? xs[r0 * XS_STRIDE + xc] : 0.0f);
                    a[s][1] = cvt_tf32(r1 < NTOK ? xs[r1 * XS_STRIDE + xc] : 0.0f);
                    a[s][2] = cvt_tf32(r0 < NTOK ? xs[r0 * XS_STRIDE + xc + 4] : 0.0f);
                    a[s][3] = cvt_tf32(r1 < NTOK ? xs[r1 * XS_STRIDE + xc + 4] : 0.0f);
                }
                #pragma unroll
                for (int t = 0; t < 9; t++) {
                    unsigned bb[2];
                    int bc = n0 + t * 8 + lg;
                    bb[0] = cvt_tf32(wp[(kb + lr) * WP1_STRIDE + bc]);
                    bb[1] = cvt_tf32(wp[(kb + 4 + lr) * WP1_STRIDE + bc]);
                    mma_tf32(d[0][t], a[0], bb);
                    mma_tf32(d[1][t], a[1], bb);
                }
            }
        }
        // epilogue: +bias, scale q, scatter to qs/ks/vs
        #pragma unroll
        for (int s = 0; s < 2; s++) {
            int r0 = m0 + s * 16 + lg, r1 = r0 + 8;
            #pragma unroll
            for (int t = 0; t < 9; t++) {
                int col  = n0 + t * 8 + 2 * lr;
                int part = col / DIMC;
                int cc   = col % DIMC;
                float* dst = (part == 0) ? qs : (part == 1) ? ks : vs;
                float sc   = (part == 0) ? QSCALE : 1.0f;
                float bv0 = b_qkv[col], bv1 = b_qkv[col + 1];
                if (r0 < NTOK) {
                    float2 o = make_float2((d[s][t][0] + bv0) * sc, (d[s][t][1] + bv1) * sc);
                    *(float2*)&dst[r0 * QKV_STRIDE + cc] = o;
                }
                if (r1 < NTOK) {
                    float2 o = make_float2((d[s][t][2] + bv0) * sc, (d[s][t][3] + bv1) * sc);
                    *(float2*)&dst[r1 * QKV_STRIDE + cc] = o;
                }
            }
        }
    }
    __syncthreads();

    // ================ phase 2a: S = q k^T + bias + mask (scalar) ================
    const float* mrow = mask + (size_t)(b & (NWMASK - 1)) * (NTOK * NTOK);
    for (int t = tid; t < 1014; t += NTHREADS) {
        int h   = t / 169;
        int rem = t % 169;
        int pg  = rem / 13, qg = rem % 13;
        float a[4][4];
        #pragma unroll
        for (int i = 0; i < 4; i++)
            #pragma unroll
            for (int j = 0; j < 4; j++) a[i][j] = 0.0f;

        int pbase[4], qbase[4];
        #pragma unroll
        for (int i = 0; i < 4; i++) {
            int p = pg * 4 + i; if (p > 48) p = 48;
            pbase[i] = p * QKV_STRIDE + h * HDIM;
        }
        #pragma unroll
        for (int j = 0; j < 4; j++) {
            int q = qg * 4 + j; if (q > 48) q = 48;
            qbase[j] = q * QKV_STRIDE + h * HDIM;
        }
        #pragma unroll
        for (int dd = 0; dd < 8; ++dd) {
            float4 qv[4], kv[4];
            #pragma unroll
            for (int i = 0; i < 4; i++) qv[i] = *(const float4*)&qs[pbase[i] + dd * 4];
            #pragma unroll
            for (int j = 0; j < 4; j++) kv[j] = *(const float4*)&ks[qbase[j] + dd * 4];
            #pragma unroll
            for (int i = 0; i < 4; i++)
                #pragma unroll
                for (int j = 0; j < 4; j++) {
                    a[i][j] = fmaf(qv[i].x, kv[j].x, a[i][j]);
                    a[i][j] = fmaf(qv[i].y, kv[j].y, a[i][j]);
                    a[i][j] = fmaf(qv[i].z, kv[j].z, a[i][j]);
                    a[i][j] = fmaf(qv[i].w, kv[j].w, a[i][j]);
                }
        }
        #pragma unroll
        for (int i = 0; i < 4; i++) {
            int p = pg * 4 + i;
            if (p < NTOK) {
                int ip = p / 7, jp = p % 7;
                #pragma unroll
                for (int j = 0; j < 4; j++) {
                    int q = qg * 4 + j;
                    if (q < NTOK) {
                        int iq = q / 7, jq = q % 7;
                        int ridx = (jp - jq + 6) * 13 + (ip - iq + 6);
                        att[(h * NTOK + p) * ATT_STRIDE + q] =
                            a[i][j] + table[ridx * HEADS + h] + mrow[p * NTOK + q];
                    }
                }
            }
        }
    }
    __syncthreads();

    // ================ phase 2b: softmax rows ================
    for (int t = tid; t < HEADS * NTOK; t += NTHREADS) {
        float* row = att + t * ATT_STRIDE;
        float m = row[0];
        for (int q = 1; q < NTOK; q++) m = fmaxf(m, row[q]);
        float s = 0.0f;
        for (int q = 0; q < NTOK; q++) {
            float e = __expf(row[q] - m);
            row[q] = e;
            s += e;
        }
        float inv = 1.0f / s;
        for (int q = 0; q < NTOK; q++) row[q] *= inv;
    }
    __syncthreads();

    // ================ phase 2c: O = S @ V (O overwrites qs) ================
    float* os = qs;
    for (int t = tid; t < 312; t += NTHREADS) {
        int h   = t / 52;
        int rem = t % 52;
        int pg  = rem / 4, dg = rem % 4;
        float4 a0[4], a1[4];
        #pragma unroll
        for (int i = 0; i < 4; i++) {
            a0[i] = make_float4(0.f, 0.f, 0.f, 0.f);
            a1[i] = make_float4(0.f, 0.f, 0.f, 0.f);
        }
        int pr[4];
        #pragma unroll
        for (int i = 0; i < 4; i++) {
            int p = pg * 4 + i; if (p > 48) p = 48;
            pr[i] = p;
        }
        for (int q = 0; q < NTOK; q++) {
            float4 v0 = *(const float4*)&vs[q * QKV_STRIDE + h * HDIM + dg * 8];
            float4 v1 = *(const float4*)&vs[q * QKV_STRIDE + h * HDIM + dg * 8 + 4];
            #pragma unroll
            for (int i = 0; i < 4; i++) {
                float sv = att[(h * NTOK + pr[i]) * ATT_STRIDE + q];
                a0[i].x = fmaf(sv, v0.x, a0[i].x);
                a0[i].y = fmaf(sv, v0.y, a0[i].y);
                a0[i].z = fmaf(sv, v0.z, a0[i].z);
                a0[i].w = fmaf(sv, v0.w, a0[i].w);
                a1[i].x = fmaf(sv, v1.x, a1[i].x);
                a1[i].y = fmaf(sv, v1.y, a1[i].y);
                a1[i].z = fmaf(sv, v1.z, a1[i].z);
                a1[i].w = fmaf(sv, v1.w, a1[i].w);
            }
        }
        #pragma unroll
        for (int i = 0; i < 4; i++) {
            int p = pg * 4 + i;
            if (p < NTOK) {
                *(float4*)&os[p * QKV_STRIDE + h * HDIM + dg * 8]     = a0[i];
                *(float4*)&os[p * QKV_STRIDE + h * HDIM + dg * 8 + 4] = a1[i];
            }
        }
    }

    // ================ phase 3: out = O @ w_proj + b_proj (TF32 MMA) ================
    {
        const int n0 = (w >> 1) * 24;       // 8 slices x 24 cols = 192
        const int m0 = (w & 1) * 32;
        float d[2][3][4];
        #pragma unroll
        for (int s = 0; s < 2; s++)
            #pragma unroll
            for (int t = 0; t < 3; t++)
                #pragma unroll
                for (int j = 0; j < 4; j++) d[s][t][j] = 0.0f;

        for (int kp = 0; kp < 12; ++kp) {
            __syncthreads();   // first iter: also fences phase-2c att reads vs wp overwrite
            for (int i = tid; i < 16 * 48; i += NTHREADS) {
                int r = i / 48, c4 = i % 48;
                *(float4*)&wp[r * WP3_STRIDE + c4 * 4] =
                    ((const float4*)w_proj)[(kp * 16 + r) * 48 + c4];
            }
            __syncthreads();
            #pragma unroll
            for (int k8 = 0; k8 < 2; ++k8) {
                const int kb = k8 * 8;
                const int xc = kp * 16 + kb + lr;
                unsigned a[2][4];
                #pragma unroll
                for (int s = 0; s < 2; s++) {
                    int r0 = m0 + s * 16 + lg, r1 = r0 + 8;
                    a[s][0] = cvt_tf32(r0 < NTOK ? os[r0 * QKV_STRIDE + xc] : 0.0f);
                    a[s][1] = cvt_tf32(r1 < NTOK ? os[r1 * QKV_STRIDE + xc] : 0.0f);
                    a[s][2] = cvt_tf32(r0 < NTOK ? os[r0 * QKV_STRIDE + xc + 4] : 0.0f);
                    a[s][3] = cvt_tf32(r1 < NTOK ? os[r1 * QKV_STRIDE + xc + 4] : 0.0f);
                }
                #pragma unroll
                for (int t = 0; t < 3; t++) {
                    unsigned bb[2];
                    int bc = n0 + t * 8 + lg;
                    bb[0] = cvt_tf32(wp[(kb + lr) * WP3_STRIDE + bc]);
                    bb[1] = cvt_tf32(wp[(kb + 4 + lr) * WP3_STRIDE + bc]);
                    mma_tf32(d[0][t], a[0], bb);
                    mma_tf32(d[1][t], a[1], bb);
                }
            }
        }
        float* og = out + (size_t)b * (NTOK * DIMC);
        #pragma unroll
        for (int s = 0; s < 2; s++) {
            int r0 = m0 + s * 16 + lg, r1 = r0 + 8;
            #pragma unroll
            for (int t = 0; t < 3; t++) {
                int col = n0 + t * 8 + 2 * lr;
                float bv0 = b_proj[col], bv1 = b_proj[col + 1];
                if (r0 < NTOK) {
                    float2 o = make_float2(d[s][t][0] + bv0, d[s][t][1] + bv1);
                    *(float2*)&og[r0 * DIMC + col] = o;
                }
                if (r1 < NTOK) {
                    float2 o = make_float2(d[s][t][2] + bv0, d[s][t][3] + bv1);
                    *(float2*)&og[r1 * DIMC + col] = o;
                }
            }
        }
    }
}

extern "C" void kernel_launch(void* const* d_in, const int* in_sizes, int n_in,
                              void* d_out, int out_size)
{
    const float* x      = (const float*)d_in[0];
    const float* mask   = (const float*)d_in[1];
    const float* w_qkv  = (const float*)d_in[2];
    const float* b_qkv  = (const float*)d_in[3];
    const float* w_proj = (const float*)d_in[4];
    const float* b_proj = (const float*)d_in[5];
    const float* table  = (const float*)d_in[6];
    float* out = (float*)d_out;

    const int smem_bytes = SMEM_FLOATS * (int)sizeof(float);
    cudaFuncSetAttribute(winattn_fused_kernel,
                         cudaFuncAttributeMaxDynamicSharedMemorySize, smem_bytes);

    winattn_fused_kernel<<<BWIN, NTHREADS, smem_bytes>>>(
        x, mask, w_qkv, b_qkv, w_proj, b_proj, table, out);
}

// round 4
// speedup vs baseline: 1.7490x; 1.3170x over previous
#include <cuda_runtime.h>
#include <math.h>

#define BWIN   4096
#define NTOK   49
#define DIMC   192
#define HEADS  6
#define HDIM   32
#define NWMASK 64
#define QSCALE 0.17677669529663687f
#define NTHREADS 512

// smem strides (floats/words), chosen for conflict-free MMA fragment LDS:
//  stride%32==4  (196): A-pattern bank = 4*lg + lr  -> 32 distinct
//  stride%32==8  (584/200): B-pattern bank = 8*lr + lg -> 32 distinct
//  stride%32==28 (60): pattern bank = 28*lg%32 + lr -> 32 distinct
#define XS_STRIDE  196
#define QKV_STRIDE 196
#define VT_STRIDE  60
#define ATT_STRIDE 60
#define WP1_STRIDE 584
#define WP3_STRIDE 200
#define KPANEL     24

#define OFF_XS 0
#define OFF_WP 9604                       // 49*196
#define OFF_B  23620                      // OFF_WP + 24*584
#define OFF_QS OFF_B
#define OFF_KS (OFF_B + 9604)
#define OFF_VT (OFF_B + 19208)
#define SMEM_WORDS (OFF_VT + 192 * 60)    // 54348 words = 217,392 B

__device__ __forceinline__ unsigned cvt_tf32(float f) {
    unsigned r;
    asm("cvt.rna.tf32.f32 %0, %1;" : "=r"(r) : "f"(f));
    return r;
}

__device__ __forceinline__ void mma_tf32(float* d, const unsigned* a, const unsigned* bb) {
    asm volatile(
        "mma.sync.aligned.m16n8k8.row.col.f32.tf32.tf32.f32 "
        "{%0,%1,%2,%3}, {%4,%5,%6,%7}, {%8,%9}, {%0,%1,%2,%3};"
        : "+f"(d[0]), "+f"(d[1]), "+f"(d[2]), "+f"(d[3])
        : "r"(a[0]), "r"(a[1]), "r"(a[2]), "r"(a[3]),
          "r"(bb[0]), "r"(bb[1]));
}

__global__ __launch_bounds__(NTHREADS, 1)
void winattn_fused_kernel(const float* __restrict__ x,
                          const float* __restrict__ mask,
                          const float* __restrict__ w_qkv,
                          const float* __restrict__ b_qkv,
                          const float* __restrict__ w_proj,
                          const float* __restrict__ b_proj,
                          const float* __restrict__ table,
                          float* __restrict__ out)
{
    extern __shared__ unsigned smu[];
    float* smf = (float*)smu;

    unsigned* xsu  = smu + OFF_XS;        // 49x196 tf32 bits (phase 1)
    unsigned* wpu  = smu + OFF_WP;        // 24x584 / 24x200 tf32 bits
    float*    attf = smf + OFF_XS;        // 6x49x60 fp32 (phase 2 overlay)
    unsigned* attu = smu + OFF_XS;        // same region, tf32 bits after softmax
    unsigned* qsu  = smu + OFF_QS;        // 49x196 q tf32 bits (later O bits)
    unsigned* ksu  = smu + OFF_KS;        // 49x196 k tf32 bits
    unsigned* vtu  = smu + OFF_VT;        // 192x60 v^T tf32 bits

    const int tid  = threadIdx.x;
    const int lane = tid & 31;
    const int w    = tid >> 5;
    const int lg   = lane >> 2;           // 0..7
    const int lr   = lane & 3;            // 0..3
    const int b    = blockIdx.x;
    const float* xg = x + (size_t)b * (NTOK * DIMC);

    // ---------------- load x window as tf32 bits ----------------
    for (int i = tid; i < NTOK * DIMC; i += NTHREADS)
        xsu[(i / DIMC) * XS_STRIDE + (i % DIMC)] = cvt_tf32(xg[i]);

    // ================ phase 1: qkv = x @ w_qkv + b_qkv (TF32 MMA) ================
    {
        const int n0 = (w >> 1) * 72;
        const int m0 = (w & 1) * 32;
        float d[2][9][4];
        #pragma unroll
        for (int s = 0; s < 2; s++)
            #pragma unroll
            for (int t = 0; t < 9; t++)
                #pragma unroll
                for (int j = 0; j < 4; j++) d[s][t][j] = 0.0f;

        for (int kp = 0; kp < 8; ++kp) {
            __syncthreads();
            for (int i = tid; i < KPANEL * 144; i += NTHREADS) {
                int r = i / 144, c4 = i % 144;
                float4 v = ((const float4*)w_qkv)[(kp * KPANEL + r) * 144 + c4];
                uint4 u = make_uint4(cvt_tf32(v.x), cvt_tf32(v.y), cvt_tf32(v.z), cvt_tf32(v.w));
                *(uint4*)&wpu[r * WP1_STRIDE + c4 * 4] = u;
            }
            __syncthreads();
            #pragma unroll
            for (int k8 = 0; k8 < 3; ++k8) {
                const int kb = k8 * 8;
                const int xc = kp * KPANEL + kb + lr;
                unsigned a[2][4];
                #pragma unroll
                for (int s = 0; s < 2; s++) {
                    int r0 = m0 + s * 16 + lg;
                    a[s][0] = xsu[r0 * XS_STRIDE + xc];
                    a[s][1] = xsu[(r0 + 8) * XS_STRIDE + xc];
                    a[s][2] = xsu[r0 * XS_STRIDE + xc + 4];
                    a[s][3] = xsu[(r0 + 8) * XS_STRIDE + xc + 4];
                }
                #pragma unroll
                for (int t = 0; t < 9; t++) {
                    unsigned bb[2];
                    int bc = n0 + t * 8 + lg;
                    bb[0] = wpu[(kb + lr) * WP1_STRIDE + bc];
                    bb[1] = wpu[(kb + 4 + lr) * WP1_STRIDE + bc];
                    mma_tf32(d[0][t], a[0], bb);
                    mma_tf32(d[1][t], a[1], bb);
                }
            }
        }
        // epilogue: +bias, scale q; store q,k as tf32 bits; v transposed tf32 bits
        #pragma unroll
        for (int s = 0; s < 2; s++) {
            int r0 = m0 + s * 16 + lg, r1 = r0 + 8;
            #pragma unroll
            for (int t = 0; t < 9; t++) {
                int col  = n0 + t * 8 + 2 * lr;
                int part = col / DIMC;
                int cc   = col % DIMC;
                float bv0 = b_qkv[col], bv1 = b_qkv[col + 1];
                if (part == 0) {
                    if (r0 < NTOK) {
                        uint2 o = make_uint2(cvt_tf32((d[s][t][0] + bv0) * QSCALE),
                                             cvt_tf32((d[s][t][1] + bv1) * QSCALE));
                        *(uint2*)&qsu[r0 * QKV_STRIDE + cc] = o;
                    }
                    if (r1 < NTOK) {
                        uint2 o = make_uint2(cvt_tf32((d[s][t][2] + bv0) * QSCALE),
                                             cvt_tf32((d[s][t][3] + bv1) * QSCALE));
                        *(uint2*)&qsu[r1 * QKV_STRIDE + cc] = o;
                    }
                } else if (part == 1) {
                    if (r0 < NTOK) {
                        uint2 o = make_uint2(cvt_tf32(d[s][t][0] + bv0),
                                             cvt_tf32(d[s][t][1] + bv1));
                        *(uint2*)&ksu[r0 * QKV_STRIDE + cc] = o;
                    }
                    if (r1 < NTOK) {
                        uint2 o = make_uint2(cvt_tf32(d[s][t][2] + bv0),
                                             cvt_tf32(d[s][t][3] + bv1));
                        *(uint2*)&ksu[r1 * QKV_STRIDE + cc] = o;
                    }
                } else {
                    if (r0 < NTOK) {
                        vtu[cc * VT_STRIDE + r0]       = cvt_tf32(d[s][t][0] + bv0);
                        vtu[(cc + 1) * VT_STRIDE + r0] = cvt_tf32(d[s][t][1] + bv1);
                    }
                    if (r1 < NTOK) {
                        vtu[cc * VT_STRIDE + r1]       = cvt_tf32(d[s][t][2] + bv0);
                        vtu[(cc + 1) * VT_STRIDE + r1] = cvt_tf32(d[s][t][3] + bv1);
                    }
                }
            }
        }
    }
    // zero-pad v^T columns 49..55 (K-padding for 2c MMA must be finite)
    for (int i = tid; i < DIMC * 7; i += NTHREADS)
        vtu[(i / 7) * VT_STRIDE + 49 + (i % 7)] = 0u;
    __syncthreads();

    // ================ phase 2a: S = q k^T + bias + mask (TF32 MMA, warps 0..11) ================
    const float* mrow = mask + (size_t)(b & (NWMASK - 1)) * (NTOK * NTOK);
    if (w < 12) {
        const int h  = w >> 1;
        const int m0 = (w & 1) * 32;
        float d[2][7][4];
        #pragma unroll
        for (int s = 0; s < 2; s++)
            #pragma unroll
            for (int t = 0; t < 7; t++)
                #pragma unroll
                for (int j = 0; j < 4; j++) d[s][t][j] = 0.0f;

        #pragma unroll
        for (int k8 = 0; k8 < 4; ++k8) {
            const int kb = k8 * 8;
            unsigned a[2][4];
            #pragma unroll
            for (int s = 0; s < 2; s++) {
                int base = (m0 + s * 16 + lg) * QKV_STRIDE + h * HDIM + kb + lr;
                a[s][0] = qsu[base];
                a[s][1] = qsu[base + 8 * QKV_STRIDE];
                a[s][2] = qsu[base + 4];
                a[s][3] = qsu[base + 8 * QKV_STRIDE + 4];
            }
            #pragma unroll
            for (int t = 0; t < 7; t++) {
                unsigned bb[2];
                int base = (t * 8 + lg) * QKV_STRIDE + h * HDIM + kb + lr;
                bb[0] = ksu[base];
                bb[1] = ksu[base + 4];
                mma_tf32(d[0][t], a[0], bb);
                mma_tf32(d[1][t], a[1], bb);
            }
        }
        // epilogue: + relative-position bias + mask, store fp32 to att
        #pragma unroll
        for (int s = 0; s < 2; s++) {
            #pragma unroll
            for (int half = 0; half < 2; half++) {
                int p = m0 + s * 16 + lg + half * 8;
                if (p < NTOK) {
                    int ip = p / 7, jp = p % 7;
                    float* arow = attf + (h * NTOK + p) * ATT_STRIDE;
                    const float* mr = mrow + p * NTOK;
                    #pragma unroll
                    for (int t = 0; t < 7; t++) {
                        #pragma unroll
                        for (int c = 0; c < 2; c++) {
                            int q = t * 8 + 2 * lr + c;
                            if (q < NTOK) {
                                int iq = q / 7, jq = q % 7;
                                int ridx = (jp - jq + 6) * 13 + (ip - iq + 6);
                                arow[q] = d[s][t][half * 2 + c]
                                          + __ldg(&table[ridx * HEADS + h]) + mr[q];
                            }
                        }
                    }
                }
            }
        }
    }
    __syncthreads();

    // ================ phase 2b: softmax rows -> tf32 prob bits + zero pad ================
    if (tid < HEADS * NTOK) {
        float* row = attf + tid * ATT_STRIDE;
        unsigned* rowu = attu + tid * ATT_STRIDE;
        float m = row[0];
        #pragma unroll 7
        for (int q = 1; q < NTOK; q++) m = fmaxf(m, row[q]);
        float e[NTOK];
        float s = 0.0f;
        #pragma unroll 7
        for (int q = 0; q < NTOK; q++) {
            e[q] = __expf(row[q] - m);
            s += e[q];
        }
        float inv = 1.0f / s;
        #pragma unroll 7
        for (int q = 0; q < NTOK; q++) rowu[q] = cvt_tf32(e[q] * inv);
        #pragma unroll
        for (int q = NTOK; q < 56; q++) rowu[q] = 0u;
    }
    __syncthreads();

    // ================ phase 2c: O = S @ V (TF32 MMA, warps 0..11; O bits -> qs) ================
    unsigned* osu = qsu;
    if (w < 12) {
        const int h  = w >> 1;
        const int m0 = (w & 1) * 32;
        float d[2][4][4];
        #pragma unroll
        for (int s = 0; s < 2; s++)
            #pragma unroll
            for (int t = 0; t < 4; t++)
                #pragma unroll
                for (int j = 0; j < 4; j++) d[s][t][j] = 0.0f;

        #pragma unroll
        for (int k8 = 0; k8 < 7; ++k8) {
            const int kb = k8 * 8;
            unsigned a[2][4];
            #pragma unroll
            for (int s = 0; s < 2; s++) {
                int base = (h * NTOK + m0 + s * 16 + lg) * ATT_STRIDE + kb + lr;
                a[s][0] = attu[base];
                a[s][1] = attu[base + 8 * ATT_STRIDE];
                a[s][2] = attu[base + 4];
                a[s][3] = attu[base + 8 * ATT_STRIDE + 4];
            }
            #pragma unroll
            for (int t = 0; t < 4; t++) {
                unsigned bb[2];
                int base = (h * HDIM + t * 8 + lg) * VT_STRIDE + kb + lr;
                bb[0] = vtu[base];
                bb[1] = vtu[base + 4];
                mma_tf32(d[0][t], a[0], bb);
                mma_tf32(d[1][t], a[1], bb);
            }
        }
        // store O as tf32 bits (A-operand of phase 3)
        #pragma unroll
        for (int s = 0; s < 2; s++) {
            int r0 = m0 + s * 16 + lg, r1 = r0 + 8;
            #pragma unroll
            for (int t = 0; t < 4; t++) {
                int dc = h * HDIM + t * 8 + 2 * lr;
                if (r0 < NTOK) {
                    uint2 o = make_uint2(cvt_tf32(d[s][t][0]), cvt_tf32(d[s][t][1]));
                    *(uint2*)&osu[r0 * QKV_STRIDE + dc] = o;
                }
                if (r1 < NTOK) {
                    uint2 o = make_uint2(cvt_tf32(d[s][t][2]), cvt_tf32(d[s][t][3]));
                    *(uint2*)&osu[r1 * QKV_STRIDE + dc] = o;
                }
            }
        }
    }

    // ================ phase 3: out = O @ w_proj + b_proj (TF32 MMA) ================
    {
        const int n0 = (w >> 1) * 24;
        const int m0 = (w & 1) * 32;
        float d[2][3][4];
        #pragma unroll
        for (int s = 0; s < 2; s++)
            #pragma unroll
            for (int t = 0; t < 3; t++)
                #pragma unroll
                for (int j = 0; j < 4; j++) d[s][t][j] = 0.0f;

        for (int kp = 0; kp < 8; ++kp) {
            __syncthreads();   // first iter also fences 2c writes / att reads vs wp overwrite
            for (int i = tid; i < KPANEL * 48; i += NTHREADS) {
                int r = i / 48, c4 = i % 48;
                float4 v = ((const float4*)w_proj)[(kp * KPANEL + r) * 48 + c4];
                uint4 u = make_uint4(cvt_tf32(v.x), cvt_tf32(v.y), cvt_tf32(v.z), cvt_tf32(v.w));
                *(uint4*)&wpu[r * WP3_STRIDE + c4 * 4] = u;
            }
            __syncthreads();
            #pragma unroll
            for (int k8 = 0; k8 < 3; ++k8) {
                const int kb = k8 * 8;
                const int xc = kp * KPANEL + kb + lr;
                unsigned a[2][4];
                #pragma unroll
                for (int s = 0; s < 2; s++) {
                    int r0 = m0 + s * 16 + lg;
                    a[s][0] = osu[r0 * QKV_STRIDE + xc];
                    a[s][1] = osu[(r0 + 8) * QKV_STRIDE + xc];
                    a[s][2] = osu[r0 * QKV_STRIDE + xc + 4];
                    a[s][3] = osu[(r0 + 8) * QKV_STRIDE + xc + 4];
                }
                #pragma unroll
                for (int t = 0; t < 3; t++) {
                    unsigned bb[2];
                    int bc = n0 + t * 8 + lg;
                    bb[0] = wpu[(kb + lr) * WP3_STRIDE + bc];
                    bb[1] = wpu[(kb + 4 + lr) * WP3_STRIDE + bc];
                    mma_tf32(d[0][t], a[0], bb);
                    mma_tf32(d[1][t], a[1], bb);
                }
            }
        }
        float* og = out + (size_t)b * (NTOK * DIMC);
        #pragma unroll
        for (int s = 0; s < 2; s++) {
            int r0 = m0 + s * 16 + lg, r1 = r0 + 8;
            #pragma unroll
            for (int t = 0; t < 3; t++) {
                int col = n0 + t * 8 + 2 * lr;
                float bv0 = b_proj[col], bv1 = b_proj[col + 1];
                if (r0 < NTOK) {
                    float2 o = make_float2(d[s][t][0] + bv0, d[s][t][1] + bv1);
                    *(float2*)&og[r0 * DIMC + col] = o;
                }
                if (r1 < NTOK) {
                    float2 o = make_float2(d[s][t][2] + bv0, d[s][t][3] + bv1);
                    *(float2*)&og[r1 * DIMC + col] = o;
                }
            }
        }
    }
}

extern "C" void kernel_launch(void* const* d_in, const int* in_sizes, int n_in,
                              void* d_out, int out_size)
{
    const float* x      = (const float*)d_in[0];
    const float* mask   = (const float*)d_in[1];
    const float* w_qkv  = (const float*)d_in[2];
    const float* b_qkv  = (const float*)d_in[3];
    const float* w_proj = (const float*)d_in[4];
    const float* b_proj = (const float*)d_in[5];
    const float* table  = (const float*)d_in[6];
    float* out = (float*)d_out;

    const int smem_bytes = SMEM_WORDS * (int)sizeof(unsigned);
    cudaFuncSetAttribute(winattn_fused_kernel,
                         cudaFuncAttributeMaxDynamicSharedMemorySize, smem_bytes);

    winattn_fused_kernel<<<BWIN, NTHREADS, smem_bytes>>>(
        x, mask, w_qkv, b_qkv, w_proj, b_proj, table, out);
}

// round 5
// speedup vs baseline: 2.1000x; 1.2006x over previous
#include <cuda_runtime.h>
#include <math.h>

#define BWIN   4096
#define NTOK   49
#define DIMC   192
#define HEADS  6
#define HDIM   32
#define NWMASK 64
#define QSCALE 0.17677669529663687f
#define NTHREADS 512

// smem strides (words), conflict-free for the MMA fragment patterns used:
//  stride%32==4  (196): A-pattern bank = 4*lg + lr    -> 32 distinct
//  stride%32==8  (584/200): B-pattern bank = 8*lr+lg  -> 32 distinct
//  stride%32==28 (60): pattern bank = 28*lg + lr      -> 32 distinct
#define XS_STRIDE  196
#define QKV_STRIDE 196
#define VT_STRIDE  60
#define ATT_STRIDE 60
#define WP1_STRIDE 584
#define WP3_STRIDE 200
#define KPANEL     24

#define OFF_XS 0
#define OFF_WP 9604                       // 49*196
#define OFF_B  23620                      // OFF_WP + 24*584
#define OFF_QS OFF_B
#define OFF_KS (OFF_B + 9604)
#define OFF_VT (OFF_B + 19208)
#define SMEM_WORDS (OFF_VT + 192 * 60)    // 54348 words = 217,392 B
// att region (tf32 prob bits): 6 heads x 64 rows x 60 = 23040 words, overlays [0, OFF_B)

__device__ __forceinline__ unsigned cvt_tf32(float f) {
    unsigned r;
    asm("cvt.rna.tf32.f32 %0, %1;" : "=r"(r) : "f"(f));
    return r;
}

__device__ __forceinline__ void mma_tf32(float* d, const unsigned* a, const unsigned* bb) {
    asm volatile(
        "mma.sync.aligned.m16n8k8.row.col.f32.tf32.tf32.f32 "
        "{%0,%1,%2,%3}, {%4,%5,%6,%7}, {%8,%9}, {%0,%1,%2,%3};"
        : "+f"(d[0]), "+f"(d[1]), "+f"(d[2]), "+f"(d[3])
        : "r"(a[0]), "r"(a[1]), "r"(a[2]), "r"(a[3]),
          "r"(bb[0]), "r"(bb[1]));
}

__global__ __launch_bounds__(NTHREADS, 1)
void winattn_fused_kernel(const float* __restrict__ x,
                          const float* __restrict__ mask,
                          const float* __restrict__ w_qkv,
                          const float* __restrict__ b_qkv,
                          const float* __restrict__ w_proj,
                          const float* __restrict__ b_proj,
                          const float* __restrict__ table,
                          float* __restrict__ out)
{
    extern __shared__ unsigned smu[];

    unsigned* xsu  = smu + OFF_XS;        // 49x196 tf32 bits (phase 1)
    unsigned* wpu  = smu + OFF_WP;        // 24x584 / 24x200 tf32 bits
    unsigned* attu = smu + OFF_XS;        // 6x64x60 tf32 prob bits (phase 2 overlay)
    unsigned* qsu  = smu + OFF_QS;        // 49x196 q tf32 bits (later O bits)
    unsigned* ksu  = smu + OFF_KS;        // 49x196 k tf32 bits
    unsigned* vtu  = smu + OFF_VT;        // 192x60 v^T tf32 bits

    const int tid  = threadIdx.x;
    const int lane = tid & 31;
    const int w    = tid >> 5;
    const int lg   = lane >> 2;
    const int lr   = lane & 3;
    const int b    = blockIdx.x;
    const float* xg = x + (size_t)b * (NTOK * DIMC);

    // ---------------- load x window as tf32 bits ----------------
    for (int i = tid; i < NTOK * DIMC; i += NTHREADS)
        xsu[(i / DIMC) * XS_STRIDE + (i % DIMC)] = cvt_tf32(xg[i]);

    // ================ phase 1: qkv = x @ w_qkv + b_qkv (TF32 MMA) ================
    {
        const int n0 = (w >> 1) * 72;
        const int m0 = (w & 1) * 32;
        float d[2][9][4];
        #pragma unroll
        for (int s = 0; s < 2; s++)
            #pragma unroll
            for (int t = 0; t < 9; t++)
                #pragma unroll
                for (int j = 0; j < 4; j++) d[s][t][j] = 0.0f;

        // register prefetch of weight panel 0 (24 rows x 576 = 3456 float4)
        float4 pre[7];
        #pragma unroll
        for (int j = 0; j < 7; j++) {
            int idx = tid + j * NTHREADS;
            if (idx < 3456) pre[j] = ((const float4*)w_qkv)[idx];
        }

        for (int kp = 0; kp < 8; ++kp) {
            __syncthreads();                       // wp free
            #pragma unroll
            for (int j = 0; j < 7; j++) {
                int idx = tid + j * NTHREADS;
                if (idx < 3456) {
                    int r = idx / 144, c4 = idx % 144;
                    *(uint4*)&wpu[r * WP1_STRIDE + c4 * 4] =
                        make_uint4(cvt_tf32(pre[j].x), cvt_tf32(pre[j].y),
                                   cvt_tf32(pre[j].z), cvt_tf32(pre[j].w));
                }
            }
            __syncthreads();                       // wp ready
            if (kp < 7) {                          // prefetch next panel (overlaps mma)
                #pragma unroll
                for (int j = 0; j < 7; j++) {
                    int idx = tid + j * NTHREADS;
                    if (idx < 3456) pre[j] = ((const float4*)w_qkv)[(kp + 1) * 3456 + idx];
                }
            }
            #pragma unroll
            for (int k8 = 0; k8 < 3; ++k8) {
                const int kb = k8 * 8;
                const int xc = kp * KPANEL + kb + lr;
                unsigned a[2][4];
                #pragma unroll
                for (int s = 0; s < 2; s++) {
                    int r0 = m0 + s * 16 + lg;
                    a[s][0] = xsu[r0 * XS_STRIDE + xc];
                    a[s][1] = xsu[(r0 + 8) * XS_STRIDE + xc];
                    a[s][2] = xsu[r0 * XS_STRIDE + xc + 4];
                    a[s][3] = xsu[(r0 + 8) * XS_STRIDE + xc + 4];
                }
                #pragma unroll
                for (int t = 0; t < 9; t++) {
                    unsigned bb[2];
                    int bc = n0 + t * 8 + lg;
                    bb[0] = wpu[(kb + lr) * WP1_STRIDE + bc];
                    bb[1] = wpu[(kb + 4 + lr) * WP1_STRIDE + bc];
                    mma_tf32(d[0][t], a[0], bb);
                    mma_tf32(d[1][t], a[1], bb);
                }
            }
        }
        // epilogue: +bias, scale q; store q,k tf32 bits; v transposed tf32 bits
        #pragma unroll
        for (int s = 0; s < 2; s++) {
            int r0 = m0 + s * 16 + lg, r1 = r0 + 8;
            #pragma unroll
            for (int t = 0; t < 9; t++) {
                int col  = n0 + t * 8 + 2 * lr;
                int part = col / DIMC;
                int cc   = col % DIMC;
                float bv0 = b_qkv[col], bv1 = b_qkv[col + 1];
                if (part == 0) {
                    if (r0 < NTOK) {
                        uint2 o = make_uint2(cvt_tf32((d[s][t][0] + bv0) * QSCALE),
                                             cvt_tf32((d[s][t][1] + bv1) * QSCALE));
                        *(uint2*)&qsu[r0 * QKV_STRIDE + cc] = o;
                    }
                    if (r1 < NTOK) {
                        uint2 o = make_uint2(cvt_tf32((d[s][t][2] + bv0) * QSCALE),
                                             cvt_tf32((d[s][t][3] + bv1) * QSCALE));
                        *(uint2*)&qsu[r1 * QKV_STRIDE + cc] = o;
                    }
                } else if (part == 1) {
                    if (r0 < NTOK) {
                        uint2 o = make_uint2(cvt_tf32(d[s][t][0] + bv0),
                                             cvt_tf32(d[s][t][1] + bv1));
                        *(uint2*)&ksu[r0 * QKV_STRIDE + cc] = o;
                    }
                    if (r1 < NTOK) {
                        uint2 o = make_uint2(cvt_tf32(d[s][t][2] + bv0),
                                             cvt_tf32(d[s][t][3] + bv1));
                        *(uint2*)&ksu[r1 * QKV_STRIDE + cc] = o;
                    }
                } else {
                    if (r0 < NTOK) {
                        vtu[cc * VT_STRIDE + r0]       = cvt_tf32(d[s][t][0] + bv0);
                        vtu[(cc + 1) * VT_STRIDE + r0] = cvt_tf32(d[s][t][1] + bv1);
                    }
                    if (r1 < NTOK) {
                        vtu[cc * VT_STRIDE + r1]       = cvt_tf32(d[s][t][2] + bv0);
                        vtu[(cc + 1) * VT_STRIDE + r1] = cvt_tf32(d[s][t][3] + bv1);
                    }
                }
            }
        }
    }
    // zero-pad v^T token-columns 49..55 (K-padding for 2c must be finite)
    for (int i = tid; i < DIMC * 7; i += NTHREADS)
        vtu[(i / 7) * VT_STRIDE + 49 + (i % 7)] = 0u;
    __syncthreads();   // fences q/k/vt + frees xs/wp region for attu

    // ====== phase 2: attention, fully within-warp (no block syncs) ======
    const float* mrow = mask + (size_t)(b & (NWMASK - 1)) * (NTOK * NTOK);
    unsigned* osu = qsu;
    if (w < 12) {
        const int h  = w >> 1;
        const int m0 = (w & 1) * 32;

        // --- 2a: S = q k^T (TF32 MMA) ---
        float d[2][7][4];
        #pragma unroll
        for (int s = 0; s < 2; s++)
            #pragma unroll
            for (int t = 0; t < 7; t++)
                #pragma unroll
                for (int j = 0; j < 4; j++) d[s][t][j] = 0.0f;

        #pragma unroll
        for (int k8 = 0; k8 < 4; ++k8) {
            const int kb = k8 * 8;
            unsigned a[2][4];
            #pragma unroll
            for (int s = 0; s < 2; s++) {
                int base = (m0 + s * 16 + lg) * QKV_STRIDE + h * HDIM + kb + lr;
                a[s][0] = qsu[base];
                a[s][1] = qsu[base + 8 * QKV_STRIDE];
                a[s][2] = qsu[base + 4];
                a[s][3] = qsu[base + 8 * QKV_STRIDE + 4];
            }
            #pragma unroll
            for (int t = 0; t < 7; t++) {
                unsigned bb[2];
                int base = (t * 8 + lg) * QKV_STRIDE + h * HDIM + kb + lr;
                bb[0] = ksu[base];
                bb[1] = ksu[base + 4];
                mma_tf32(d[0][t], a[0], bb);
                mma_tf32(d[1][t], a[1], bb);
            }
        }

        // --- bias + mask + softmax in registers (quad butterfly) ---
        #pragma unroll
        for (int s = 0; s < 2; s++) {
            #pragma unroll
            for (int half = 0; half < 2; half++) {
                int p = m0 + s * 16 + lg + 8 * half;     // quad-uniform
                float mx = -1e30f;
                if (p < NTOK) {
                    int ip = p / 7, jp = p % 7;
                    const float* mr = mrow + p * NTOK;
                    #pragma unroll
                    for (int t = 0; t < 7; t++) {
                        #pragma unroll
                        for (int c = 0; c < 2; c++) {
                            int q = t * 8 + 2 * lr + c;
                            float v = -1e30f;
                            if (q < NTOK) {
                                int iq = q / 7, jq = q % 7;
                                int ridx = (jp - jq + 6) * 13 + (ip - iq + 6);
                                v = d[s][t][2 * half + c]
                                    + __ldg(&table[ridx * HEADS + h]) + mr[q];
                            }
                            d[s][t][2 * half + c] = v;
                            mx = fmaxf(mx, v);
                        }
                    }
                }
                mx = fmaxf(mx, __shfl_xor_sync(0xffffffffu, mx, 1));
                mx = fmaxf(mx, __shfl_xor_sync(0xffffffffu, mx, 2));
                float sum = 0.0f;
                if (p < NTOK) {
                    #pragma unroll
                    for (int t = 0; t < 7; t++) {
                        #pragma unroll
                        for (int c = 0; c < 2; c++) {
                            int q = t * 8 + 2 * lr + c;
                            float e = (q < NTOK) ? __expf(d[s][t][2 * half + c] - mx) : 0.0f;
                            d[s][t][2 * half + c] = e;
                            sum += e;
                        }
                    }
                }
                sum += __shfl_xor_sync(0xffffffffu, sum, 1);
                sum += __shfl_xor_sync(0xffffffffu, sum, 2);
                float inv = 1.0f / sum;
                unsigned* arow = attu + (h * 64 + p) * ATT_STRIDE;
                #pragma unroll
                for (int t = 0; t < 7; t++) {
                    #pragma unroll
                    for (int c = 0; c < 2; c++) {
                        int q = t * 8 + 2 * lr + c;
                        unsigned bits = 0u;
                        if (p < NTOK && q < NTOK)
                            bits = cvt_tf32(d[s][t][2 * half + c] * inv);
                        arow[q] = bits;
                    }
                }
            }
        }
        __syncwarp();   // same warp re-reads its prob rows in A-frag layout

        // --- 2c: O = P @ V (TF32 MMA), O bits overwrite q region ---
        float o[2][4][4];
        #pragma unroll
        for (int s = 0; s < 2; s++)
            #pragma unroll
            for (int t = 0; t < 4; t++)
                #pragma unroll
                for (int j = 0; j < 4; j++) o[s][t][j] = 0.0f;

        #pragma unroll
        for (int k8 = 0; k8 < 7; ++k8) {
            const int kb = k8 * 8;
            unsigned a[2][4];
            #pragma unroll
            for (int s = 0; s < 2; s++) {
                int base = (h * 64 + m0 + s * 16 + lg) * ATT_STRIDE + kb + lr;
                a[s][0] = attu[base];
                a[s][1] = attu[base + 8 * ATT_STRIDE];
                a[s][2] = attu[base + 4];
                a[s][3] = attu[base + 8 * ATT_STRIDE + 4];
            }
            #pragma unroll
            for (int t = 0; t < 4; t++) {
                unsigned bb[2];
                int base = (h * HDIM + t * 8 + lg) * VT_STRIDE + kb + lr;
                bb[0] = vtu[base];
                bb[1] = vtu[base + 4];
                mma_tf32(o[0][t], a[0], bb);
                mma_tf32(o[1][t], a[1], bb);
            }
        }
        #pragma unroll
        for (int s = 0; s < 2; s++) {
            int r0 = m0 + s * 16 + lg, r1 = r0 + 8;
            #pragma unroll
            for (int t = 0; t < 4; t++) {
                int dc = h * HDIM + t * 8 + 2 * lr;
                if (r0 < NTOK) {
                    uint2 ov = make_uint2(cvt_tf32(o[s][t][0]), cvt_tf32(o[s][t][1]));
                    *(uint2*)&osu[r0 * QKV_STRIDE + dc] = ov;
                }
                if (r1 < NTOK) {
                    uint2 ov = make_uint2(cvt_tf32(o[s][t][2]), cvt_tf32(o[s][t][3]));
                    *(uint2*)&osu[r1 * QKV_STRIDE + dc] = ov;
                }
            }
        }
    }

    // ================ phase 3: out = O @ w_proj + b_proj (TF32 MMA) ================
    {
        const int n0 = (w >> 1) * 24;
        const int m0 = (w & 1) * 32;
        float d[2][3][4];
        #pragma unroll
        for (int s = 0; s < 2; s++)
            #pragma unroll
            for (int t = 0; t < 3; t++)
                #pragma unroll
                for (int j = 0; j < 4; j++) d[s][t][j] = 0.0f;

        // prefetch proj panel 0 (24 x 192 = 1152 float4)
        float4 pre[3];
        #pragma unroll
        for (int j = 0; j < 3; j++) {
            int idx = tid + j * NTHREADS;
            if (idx < 1152) pre[j] = ((const float4*)w_proj)[idx];
        }

        for (int kp = 0; kp < 8; ++kp) {
            __syncthreads();   // first iter also fences 2c O writes vs wp overwrite
            #pragma unroll
            for (int j = 0; j < 3; j++) {
                int idx = tid + j * NTHREADS;
                if (idx < 1152) {
                    int r = idx / 48, c4 = idx % 48;
                    *(uint4*)&wpu[r * WP3_STRIDE + c4 * 4] =
                        make_uint4(cvt_tf32(pre[j].x), cvt_tf32(pre[j].y),
                                   cvt_tf32(pre[j].z), cvt_tf32(pre[j].w));
                }
            }
            __syncthreads();
            if (kp < 7) {
                #pragma unroll
                for (int j = 0; j < 3; j++) {
                    int idx = tid + j * NTHREADS;
                    if (idx < 1152) pre[j] = ((const float4*)w_proj)[(kp + 1) * 1152 + idx];
                }
            }
            #pragma unroll
            for (int k8 = 0; k8 < 3; ++k8) {
                const int kb = k8 * 8;
                const int xc = kp * KPANEL + kb + lr;
                unsigned a[2][4];
                #pragma unroll
                for (int s = 0; s < 2; s++) {
                    int r0 = m0 + s * 16 + lg;
                    a[s][0] = osu[r0 * QKV_STRIDE + xc];
                    a[s][1] = osu[(r0 + 8) * QKV_STRIDE + xc];
                    a[s][2] = osu[r0 * QKV_STRIDE + xc + 4];
                    a[s][3] = osu[(r0 + 8) * QKV_STRIDE + xc + 4];
                }
                #pragma unroll
                for (int t = 0; t < 3; t++) {
                    unsigned bb[2];
                    int bc = n0 + t * 8 + lg;
                    bb[0] = wpu[(kb + lr) * WP3_STRIDE + bc];
                    bb[1] = wpu[(kb + 4 + lr) * WP3_STRIDE + bc];
                    mma_tf32(d[0][t], a[0], bb);
                    mma_tf32(d[1][t], a[1], bb);
                }
            }
        }
        float* og = out + (size_t)b * (NTOK * DIMC);
        #pragma unroll
        for (int s = 0; s < 2; s++) {
            int r0 = m0 + s * 16 + lg, r1 = r0 + 8;
            #pragma unroll
            for (int t = 0; t < 3; t++) {
                int col = n0 + t * 8 + 2 * lr;
                float bv0 = b_proj[col], bv1 = b_proj[col + 1];
                if (r0 < NTOK) {
                    float2 ov = make_float2(d[s][t][0] + bv0, d[s][t][1] + bv1);
                    *(float2*)&og[r0 * DIMC + col] = ov;
                }
                if (r1 < NTOK) {
                    float2 ov = make_float2(d[s][t][2] + bv0, d[s][t][3] + bv1);
                    *(float2*)&og[r1 * DIMC + col] = ov;
                }
            }
        }
    }
}

extern "C" void kernel_launch(void* const* d_in, const int* in_sizes, int n_in,
                              void* d_out, int out_size)
{
    const float* x      = (const float*)d_in[0];
    const float* mask   = (const float*)d_in[1];
    const float* w_qkv  = (const float*)d_in[2];
    const float* b_qkv  = (const float*)d_in[3];
    const float* w_proj = (const float*)d_in[4];
    const float* b_proj = (const float*)d_in[5];
    const float* table  = (const float*)d_in[6];
    float* out = (float*)d_out;

    const int smem_bytes = SMEM_WORDS * (int)sizeof(unsigned);
    cudaFuncSetAttribute(winattn_fused_kernel,
                         cudaFuncAttributeMaxDynamicSharedMemorySize, smem_bytes);

    winattn_fused_kernel<<<BWIN, NTHREADS, smem_bytes>>>(
        x, mask, w_qkv, b_qkv, w_proj, b_proj, table, out);
}

// round 6
// speedup vs baseline: 2.3920x; 1.1391x over previous
#include <cuda_runtime.h>
#include <math.h>

#define BWIN   4096
#define NTOK   49
#define DIMC   192
#define HEADS  6
#define HDIM   32
#define NWMASK 64
#define QSCALE 0.17677669529663687f
#define NTHREADS 512

// smem strides (words), conflict-free for the MMA fragment patterns used:
//  stride%32==4  (196): A-pattern bank = 4*lg + lr    -> 32 distinct
//  stride%32==8  (584/200): B-pattern bank = 8*lr+lg  -> 32 distinct
//  stride%32==28 (60): pattern bank = 28*lg + lr      -> 32 distinct
#define XS_STRIDE  196
#define QKV_STRIDE 196
#define VT_STRIDE  60
#define ATT_STRIDE 60
#define WP1_STRIDE 584
#define WP3_STRIDE 200
#define KPANEL     24

#define OFF_XS 0
#define OFF_WP 9604                       // 49*196
#define OFF_B  23620                      // OFF_WP + 24*584
#define OFF_QS OFF_B
#define OFF_KS (OFF_B + 9604)
#define OFF_VT (OFF_B + 19208)
#define SMEM_WORDS (OFF_VT + 192 * 60)    // 54348 words = 217,392 B
// att region (tf32 prob bits): 6 heads x 64 rows x 60 = 23040 words, overlays [0, OFF_B)

// ---- precomputed (prep kernel) ----
__device__ unsigned g_wqkv[DIMC * 3 * DIMC];        // tf32 bits, row-major [192][576]
__device__ unsigned g_wproj[DIMC * DIMC];           // tf32 bits, [192][192]
__device__ float    g_bias[HEADS * NTOK * 56];      // expanded rel-pos bias [h][p][56]

__device__ __forceinline__ unsigned cvt_tf32(float f) {
    unsigned r;
    asm("cvt.rna.tf32.f32 %0, %1;" : "=r"(r) : "f"(f));
    return r;
}

__device__ __forceinline__ void mma_tf32(float* d, const unsigned* a, const unsigned* bb) {
    asm volatile(
        "mma.sync.aligned.m16n8k8.row.col.f32.tf32.tf32.f32 "
        "{%0,%1,%2,%3}, {%4,%5,%6,%7}, {%8,%9}, {%0,%1,%2,%3};"
        : "+f"(d[0]), "+f"(d[1]), "+f"(d[2]), "+f"(d[3])
        : "r"(a[0]), "r"(a[1]), "r"(a[2]), "r"(a[3]),
          "r"(bb[0]), "r"(bb[1]));
}

__global__ void prep_kernel(const float* __restrict__ w_qkv,
                            const float* __restrict__ w_proj,
                            const float* __restrict__ table)
{
    const int stride = gridDim.x * blockDim.x;
    const int tid0 = blockIdx.x * blockDim.x + threadIdx.x;
    for (int i = tid0; i < DIMC * 3 * DIMC; i += stride) g_wqkv[i] = cvt_tf32(w_qkv[i]);
    for (int i = tid0; i < DIMC * DIMC; i += stride)     g_wproj[i] = cvt_tf32(w_proj[i]);
    for (int i = tid0; i < HEADS * NTOK * NTOK; i += stride) {
        int h = i / (NTOK * NTOK);
        int r = i % (NTOK * NTOK);
        int p = r / NTOK, q = r % NTOK;
        int ip = p / 7, jp = p % 7, iq = q / 7, jq = q % 7;
        int ridx = (jp - jq + 6) * 13 + (ip - iq + 6);
        g_bias[(h * NTOK + p) * 56 + q] = table[ridx * HEADS + h];
    }
}

__global__ __launch_bounds__(NTHREADS, 1)
void winattn_fused_kernel(const float* __restrict__ x,
                          const float* __restrict__ mask,
                          const float* __restrict__ b_qkv,
                          const float* __restrict__ b_proj,
                          float* __restrict__ out)
{
    extern __shared__ unsigned smu[];

    unsigned* xsu  = smu + OFF_XS;        // 49x196 tf32 bits (phase 1)
    unsigned* wpu  = smu + OFF_WP;        // 24x584 / 24x200 tf32 bits
    unsigned* attu = smu + OFF_XS;        // 6x64x60 tf32 prob bits (phase 2 overlay)
    unsigned* qsu  = smu + OFF_QS;        // 49x196 q tf32 bits (later O bits)
    unsigned* ksu  = smu + OFF_KS;        // 49x196 k tf32 bits
    unsigned* vtu  = smu + OFF_VT;        // 192x60 v^T tf32 bits

    const int tid  = threadIdx.x;
    const int lane = tid & 31;
    const int w    = tid >> 5;
    const int lg   = lane >> 2;
    const int lr   = lane & 3;
    const int b    = blockIdx.x;
    const float* xg = x + (size_t)b * (NTOK * DIMC);

    // ---------------- load x window as tf32 bits ----------------
    for (int i = tid; i < NTOK * DIMC; i += NTHREADS)
        xsu[(i / DIMC) * XS_STRIDE + (i % DIMC)] = cvt_tf32(xg[i]);

    // ================ phase 1: qkv = x @ w_qkv + b_qkv (TF32 MMA) ================
    {
        const int n0 = (w >> 1) * 72;
        const int m0 = (w & 1) * 32;
        float d[2][9][4];
        #pragma unroll
        for (int s = 0; s < 2; s++)
            #pragma unroll
            for (int t = 0; t < 9; t++)
                #pragma unroll
                for (int j = 0; j < 4; j++) d[s][t][j] = 0.0f;

        // register prefetch of pre-converted weight panel 0 (24x576 = 3456 uint4)
        uint4 pre[7];
        #pragma unroll
        for (int j = 0; j < 7; j++) {
            int idx = tid + j * NTHREADS;
            if (idx < 3456) pre[j] = ((const uint4*)g_wqkv)[idx];
        }

        for (int kp = 0; kp < 8; ++kp) {
            __syncthreads();                       // wp free
            #pragma unroll
            for (int j = 0; j < 7; j++) {
                int idx = tid + j * NTHREADS;
                if (idx < 3456) {
                    int r = idx / 144, c4 = idx % 144;
                    *(uint4*)&wpu[r * WP1_STRIDE + c4 * 4] = pre[j];
                }
            }
            __syncthreads();                       // wp ready
            if (kp < 7) {                          // prefetch next panel (overlaps mma)
                #pragma unroll
                for (int j = 0; j < 7; j++) {
                    int idx = tid + j * NTHREADS;
                    if (idx < 3456) pre[j] = ((const uint4*)g_wqkv)[(kp + 1) * 3456 + idx];
                }
            }
            #pragma unroll
            for (int k8 = 0; k8 < 3; ++k8) {
                const int kb = k8 * 8;
                const int xc = kp * KPANEL + kb + lr;
                unsigned a[2][4];
                #pragma unroll
                for (int s = 0; s < 2; s++) {
                    int r0 = m0 + s * 16 + lg;
                    a[s][0] = xsu[r0 * XS_STRIDE + xc];
                    a[s][1] = xsu[(r0 + 8) * XS_STRIDE + xc];
                    a[s][2] = xsu[r0 * XS_STRIDE + xc + 4];
                    a[s][3] = xsu[(r0 + 8) * XS_STRIDE + xc + 4];
                }
                #pragma unroll
                for (int t = 0; t < 9; t++) {
                    unsigned bb[2];
                    int bc = n0 + t * 8 + lg;
                    bb[0] = wpu[(kb + lr) * WP1_STRIDE + bc];
                    bb[1] = wpu[(kb + 4 + lr) * WP1_STRIDE + bc];
                    mma_tf32(d[0][t], a[0], bb);
                    mma_tf32(d[1][t], a[1], bb);
                }
            }
        }
        // epilogue: +bias, scale q; store q,k tf32 bits; v transposed tf32 bits
        #pragma unroll
        for (int s = 0; s < 2; s++) {
            int r0 = m0 + s * 16 + lg, r1 = r0 + 8;
            #pragma unroll
            for (int t = 0; t < 9; t++) {
                int col  = n0 + t * 8 + 2 * lr;
                int part = col / DIMC;
                int cc   = col % DIMC;
                float bv0 = b_qkv[col], bv1 = b_qkv[col + 1];
                if (part == 0) {
                    if (r0 < NTOK) {
                        uint2 o = make_uint2(cvt_tf32((d[s][t][0] + bv0) * QSCALE),
                                             cvt_tf32((d[s][t][1] + bv1) * QSCALE));
                        *(uint2*)&qsu[r0 * QKV_STRIDE + cc] = o;
                    }
                    if (r1 < NTOK) {
                        uint2 o = make_uint2(cvt_tf32((d[s][t][2] + bv0) * QSCALE),
                                             cvt_tf32((d[s][t][3] + bv1) * QSCALE));
                        *(uint2*)&qsu[r1 * QKV_STRIDE + cc] = o;
                    }
                } else if (part == 1) {
                    if (r0 < NTOK) {
                        uint2 o = make_uint2(cvt_tf32(d[s][t][0] + bv0),
                                             cvt_tf32(d[s][t][1] + bv1));
                        *(uint2*)&ksu[r0 * QKV_STRIDE + cc] = o;
                    }
                    if (r1 < NTOK) {
                        uint2 o = make_uint2(cvt_tf32(d[s][t][2] + bv0),
                                             cvt_tf32(d[s][t][3] + bv1));
                        *(uint2*)&ksu[r1 * QKV_STRIDE + cc] = o;
                    }
                } else {
                    if (r0 < NTOK) {
                        vtu[cc * VT_STRIDE + r0]       = cvt_tf32(d[s][t][0] + bv0);
                        vtu[(cc + 1) * VT_STRIDE + r0] = cvt_tf32(d[s][t][1] + bv1);
                    }
                    if (r1 < NTOK) {
                        vtu[cc * VT_STRIDE + r1]       = cvt_tf32(d[s][t][2] + bv0);
                        vtu[(cc + 1) * VT_STRIDE + r1] = cvt_tf32(d[s][t][3] + bv1);
                    }
                }
            }
        }
    }
    // zero-pad v^T token-columns 49..55 (K-padding for 2c must be finite)
    for (int i = tid; i < DIMC * 7; i += NTHREADS)
        vtu[(i / 7) * VT_STRIDE + 49 + (i % 7)] = 0u;
    __syncthreads();   // fences q/k/vt + frees xs/wp region for attu

    // ====== phase 2: attention, fully within-warp (no block syncs) ======
    const float* mrow = mask + (size_t)(b & (NWMASK - 1)) * (NTOK * NTOK);
    unsigned* osu = qsu;
    if (w < 12) {
        const int h  = w >> 1;
        const int m0 = (w & 1) * 32;

        // --- 2a: S = q k^T (TF32 MMA) ---
        float d[2][7][4];
        #pragma unroll
        for (int s = 0; s < 2; s++)
            #pragma unroll
            for (int t = 0; t < 7; t++)
                #pragma unroll
                for (int j = 0; j < 4; j++) d[s][t][j] = 0.0f;

        #pragma unroll
        for (int k8 = 0; k8 < 4; ++k8) {
            const int kb = k8 * 8;
            unsigned a[2][4];
            #pragma unroll
            for (int s = 0; s < 2; s++) {
                int base = (m0 + s * 16 + lg) * QKV_STRIDE + h * HDIM + kb + lr;
                a[s][0] = qsu[base];
                a[s][1] = qsu[base + 8 * QKV_STRIDE];
                a[s][2] = qsu[base + 4];
                a[s][3] = qsu[base + 8 * QKV_STRIDE + 4];
            }
            #pragma unroll
            for (int t = 0; t < 7; t++) {
                unsigned bb[2];
                int base = (t * 8 + lg) * QKV_STRIDE + h * HDIM + kb + lr;
                bb[0] = ksu[base];
                bb[1] = ksu[base + 4];
                mma_tf32(d[0][t], a[0], bb);
                mma_tf32(d[1][t], a[1], bb);
            }
        }

        // --- bias + mask + softmax in registers (quad butterfly) ---
        #pragma unroll
        for (int s = 0; s < 2; s++) {
            #pragma unroll
            for (int half = 0; half < 2; half++) {
                int p = m0 + s * 16 + lg + 8 * half;     // quad-uniform
                float mx = -1e30f;
                if (p < NTOK) {
                    const float* brow = g_bias + (h * NTOK + p) * 56;
                    const float* mr   = mrow + p * NTOK;
                    #pragma unroll
                    for (int t = 0; t < 7; t++) {
                        int q0 = t * 8 + 2 * lr;
                        float2 bv = *(const float2*)&brow[q0];
                        float v0 = -1e30f, v1 = -1e30f;
                        if (q0 < NTOK)
                            v0 = d[s][t][2 * half]     + bv.x + mr[q0];
                        if (q0 + 1 < NTOK)
                            v1 = d[s][t][2 * half + 1] + bv.y + mr[q0 + 1];
                        d[s][t][2 * half]     = v0;
                        d[s][t][2 * half + 1] = v1;
                        mx = fmaxf(mx, fmaxf(v0, v1));
                    }
                }
                mx = fmaxf(mx, __shfl_xor_sync(0xffffffffu, mx, 1));
                mx = fmaxf(mx, __shfl_xor_sync(0xffffffffu, mx, 2));
                float sum = 0.0f;
                if (p < NTOK) {
                    #pragma unroll
                    for (int t = 0; t < 7; t++) {
                        #pragma unroll
                        for (int c = 0; c < 2; c++) {
                            int q = t * 8 + 2 * lr + c;
                            float e = (q < NTOK) ? __expf(d[s][t][2 * half + c] - mx) : 0.0f;
                            d[s][t][2 * half + c] = e;
                            sum += e;
                        }
                    }
                }
                sum += __shfl_xor_sync(0xffffffffu, sum, 1);
                sum += __shfl_xor_sync(0xffffffffu, sum, 2);
                if (p < NTOK) {
                    float inv = 1.0f / sum;
                    unsigned* arow = attu + (h * 64 + p) * ATT_STRIDE;
                    #pragma unroll
                    for (int t = 0; t < 7; t++) {
                        int q0 = t * 8 + 2 * lr;
                        uint2 bits = make_uint2(0u, 0u);
                        if (q0 < NTOK)     bits.x = cvt_tf32(d[s][t][2 * half] * inv);
                        if (q0 + 1 < NTOK) bits.y = cvt_tf32(d[s][t][2 * half + 1] * inv);
                        *(uint2*)&arow[q0] = bits;
                    }
                } else {
                    // dead rows must be finite for the 2c A-fragments (stale smem may be NaN)
                    unsigned* arow = attu + (h * 64 + p) * ATT_STRIDE;
                    #pragma unroll
                    for (int t = 0; t < 7; t++)
                        *(uint2*)&arow[t * 8 + 2 * lr] = make_uint2(0u, 0u);
                }
            }
        }
        __syncwarp();   // same warp re-reads its prob rows in A-frag layout

        // --- 2c: O = P @ V (TF32 MMA), O bits overwrite q region ---
        float o[2][4][4];
        #pragma unroll
        for (int s = 0; s < 2; s++)
            #pragma unroll
            for (int t = 0; t < 4; t++)
                #pragma unroll
                for (int j = 0; j < 4; j++) o[s][t][j] = 0.0f;

        #pragma unroll
        for (int k8 = 0; k8 < 7; ++k8) {
            const int kb = k8 * 8;
            unsigned a[2][4];
            #pragma unroll
            for (int s = 0; s < 2; s++) {
                int base = (h * 64 + m0 + s * 16 + lg) * ATT_STRIDE + kb + lr;
                a[s][0] = attu[base];
                a[s][1] = attu[base + 8 * ATT_STRIDE];
                a[s][2] = attu[base + 4];
                a[s][3] = attu[base + 8 * ATT_STRIDE + 4];
            }
            #pragma unroll
            for (int t = 0; t < 4; t++) {
                unsigned bb[2];
                int base = (h * HDIM + t * 8 + lg) * VT_STRIDE + kb + lr;
                bb[0] = vtu[base];
                bb[1] = vtu[base + 4];
                mma_tf32(o[0][t], a[0], bb);
                mma_tf32(o[1][t], a[1], bb);
            }
        }
        #pragma unroll
        for (int s = 0; s < 2; s++) {
            int r0 = m0 + s * 16 + lg, r1 = r0 + 8;
            #pragma unroll
            for (int t = 0; t < 4; t++) {
                int dc = h * HDIM + t * 8 + 2 * lr;
                if (r0 < NTOK) {
                    uint2 ov = make_uint2(cvt_tf32(o[s][t][0]), cvt_tf32(o[s][t][1]));
                    *(uint2*)&osu[r0 * QKV_STRIDE + dc] = ov;
                }
                if (r1 < NTOK) {
                    uint2 ov = make_uint2(cvt_tf32(o[s][t][2]), cvt_tf32(o[s][t][3]));
                    *(uint2*)&osu[r1 * QKV_STRIDE + dc] = ov;
                }
            }
        }
    }

    // ================ phase 3: out = O @ w_proj + b_proj (TF32 MMA) ================
    {
        const int n0 = (w >> 1) * 24;
        const int m0 = (w & 1) * 32;
        float d[2][3][4];
        #pragma unroll
        for (int s = 0; s < 2; s++)
            #pragma unroll
            for (int t = 0; t < 3; t++)
                #pragma unroll
                for (int j = 0; j < 4; j++) d[s][t][j] = 0.0f;

        // prefetch pre-converted proj panel 0 (24x192 = 1152 uint4)
        uint4 pre[3];
        #pragma unroll
        for (int j = 0; j < 3; j++) {
            int idx = tid + j * NTHREADS;
            if (idx < 1152) pre[j] = ((const uint4*)g_wproj)[idx];
        }

        for (int kp = 0; kp < 8; ++kp) {
            __syncthreads();   // first iter also fences 2c O writes vs wp overwrite
            #pragma unroll
            for (int j = 0; j < 3; j++) {
                int idx = tid + j * NTHREADS;
                if (idx < 1152) {
                    int r = idx / 48, c4 = idx % 48;
                    *(uint4*)&wpu[r * WP3_STRIDE + c4 * 4] = pre[j];
                }
            }
            __syncthreads();
            if (kp < 7) {
                #pragma unroll
                for (int j = 0; j < 3; j++) {
                    int idx = tid + j * NTHREADS;
                    if (idx < 1152) pre[j] = ((const uint4*)g_wproj)[(kp + 1) * 1152 + idx];
                }
            }
            #pragma unroll
            for (int k8 = 0; k8 < 3; ++k8) {
                const int kb = k8 * 8;
                const int xc = kp * KPANEL + kb + lr;
                unsigned a[2][4];
                #pragma unroll
                for (int s = 0; s < 2; s++) {
                    int r0 = m0 + s * 16 + lg;
                    a[s][0] = osu[r0 * QKV_STRIDE + xc];
                    a[s][1] = osu[(r0 + 8) * QKV_STRIDE + xc];
                    a[s][2] = osu[r0 * QKV_STRIDE + xc + 4];
                    a[s][3] = osu[(r0 + 8) * QKV_STRIDE + xc + 4];
                }
                #pragma unroll
                for (int t = 0; t < 3; t++) {
                    unsigned bb[2];
                    int bc = n0 + t * 8 + lg;
                    bb[0] = wpu[(kb + lr) * WP3_STRIDE + bc];
                    bb[1] = wpu[(kb + 4 + lr) * WP3_STRIDE + bc];
                    mma_tf32(d[0][t], a[0], bb);
                    mma_tf32(d[1][t], a[1], bb);
                }
            }
        }
        float* og = out + (size_t)b * (NTOK * DIMC);
        #pragma unroll
        for (int s = 0; s < 2; s++) {
            int r0 = m0 + s * 16 + lg, r1 = r0 + 8;
            #pragma unroll
            for (int t = 0; t < 3; t++) {
                int col = n0 + t * 8 + 2 * lr;
                float bv0 = b_proj[col], bv1 = b_proj[col + 1];
                if (r0 < NTOK) {
                    float2 ov = make_float2(d[s][t][0] + bv0, d[s][t][1] + bv1);
                    *(float2*)&og[r0 * DIMC + col] = ov;
                }
                if (r1 < NTOK) {
                    float2 ov = make_float2(d[s][t][2] + bv0, d[s][t][3] + bv1);
                    *(float2*)&og[r1 * DIMC + col] = ov;
                }
            }
        }
    }
}

extern "C" void kernel_launch(void* const* d_in, const int* in_sizes, int n_in,
                              void* d_out, int out_size)
{
    const float* x      = (const float*)d_in[0];
    const float* mask   = (const float*)d_in[1];
    const float* w_qkv  = (const float*)d_in[2];
    const float* b_qkv  = (const float*)d_in[3];
    const float* w_proj = (const float*)d_in[4];
    const float* b_proj = (const float*)d_in[5];
    const float* table  = (const float*)d_in[6];
    float* out = (float*)d_out;

    prep_kernel<<<148, 256>>>(w_qkv, w_proj, table);

    const int smem_bytes = SMEM_WORDS * (int)sizeof(unsigned);
    cudaFuncSetAttribute(winattn_fused_kernel,
                         cudaFuncAttributeMaxDynamicSharedMemorySize, smem_bytes);

    winattn_fused_kernel<<<BWIN, NTHREADS, smem_bytes>>>(
        x, mask, b_qkv, b_proj, out);
}

// round 7
// speedup vs baseline: 2.6857x; 1.1228x over previous
#include <cuda_runtime.h>
#include <math.h>

#define BWIN   4096
#define NTOK   49
#define DIMC   192
#define HEADS  6
#define HDIM   32
#define NWMASK 64
#define QSCALE 0.17677669529663687f
#define NTHREADS 512

// smem strides (words), conflict-free for the MMA fragment patterns used:
//  stride%32==4  (196): A-pattern bank = 4*lg + lr    -> 32 distinct
//  stride%32==28 (60): pattern bank = 28*lg + lr      -> 32 distinct
#define XS_STRIDE  196
#define QKV_STRIDE 196
#define VT_STRIDE  60
#define ATT_STRIDE 60

// smem layout (words). Region0 [0,17640): xs 49x196 in phase 1, att 6x49x60 in phase 2.
#define OFF_QS 17640
#define OFF_KS 27244                       // +49*196
#define OFF_VT 36848                       // +49*196
#define SMEM_WORDS (36848 + 192 * 60)      // 48368 words = 193,472 B

// ---- precomputed by prep kernel ----
// B-operands pre-swizzled into MMA fragment order (tf32 bits):
//  g_wfrag1[ns(8)][k8(24)][t(9)][lane(32)] = { w_qkv[k8*8+lr][ns*72+t*8+lg],
//                                              w_qkv[k8*8+4+lr][same col] }
__device__ uint2 g_wfrag1[8 * 24 * 9 * 32];
__device__ uint2 g_wfrag3[8 * 24 * 3 * 32];
__device__ float g_bias[HEADS * NTOK * 56];   // expanded rel-pos bias [h][p][56]

__device__ __forceinline__ unsigned cvt_tf32(float f) {
    unsigned r;
    asm("cvt.rna.tf32.f32 %0, %1;" : "=r"(r) : "f"(f));
    return r;
}

__device__ __forceinline__ void mma_tf32(float* d, const unsigned* a, const unsigned* bb) {
    asm volatile(
        "mma.sync.aligned.m16n8k8.row.col.f32.tf32.tf32.f32 "
        "{%0,%1,%2,%3}, {%4,%5,%6,%7}, {%8,%9}, {%0,%1,%2,%3};"
        : "+f"(d[0]), "+f"(d[1]), "+f"(d[2]), "+f"(d[3])
        : "r"(a[0]), "r"(a[1]), "r"(a[2]), "r"(a[3]),
          "r"(bb[0]), "r"(bb[1]));
}

__global__ void prep_kernel(const float* __restrict__ w_qkv,
                            const float* __restrict__ w_proj,
                            const float* __restrict__ table)
{
    const int stride = gridDim.x * blockDim.x;
    const int tid0 = blockIdx.x * blockDim.x + threadIdx.x;

    for (int i = tid0; i < 8 * 24 * 9 * 32; i += stride) {
        int lane = i & 31;
        int t    = (i >> 5) % 9;
        int k8   = (i / 288) % 24;
        int ns   = i / 6912;
        int lr = lane & 3, lg = lane >> 2;
        int col = ns * 72 + t * 8 + lg;
        int k0  = k8 * 8 + lr;
        g_wfrag1[i] = make_uint2(cvt_tf32(w_qkv[k0 * 576 + col]),
                                 cvt_tf32(w_qkv[(k0 + 4) * 576 + col]));
    }
    for (int i = tid0; i < 8 * 24 * 3 * 32; i += stride) {
        int lane = i & 31;
        int t    = (i >> 5) % 3;
        int k8   = (i / 96) % 24;
        int ns   = i / 2304;
        int lr = lane & 3, lg = lane >> 2;
        int col = ns * 24 + t * 8 + lg;
        int k0  = k8 * 8 + lr;
        g_wfrag3[i] = make_uint2(cvt_tf32(w_proj[k0 * 192 + col]),
                                 cvt_tf32(w_proj[(k0 + 4) * 192 + col]));
    }
    for (int i = tid0; i < HEADS * NTOK * NTOK; i += stride) {
        int h = i / (NTOK * NTOK);
        int r = i % (NTOK * NTOK);
        int p = r / NTOK, q = r % NTOK;
        int ip = p / 7, jp = p % 7, iq = q / 7, jq = q % 7;
        int ridx = (jp - jq + 6) * 13 + (ip - iq + 6);
        g_bias[(h * NTOK + p) * 56 + q] = table[ridx * HEADS + h];
    }
}

__global__ __launch_bounds__(NTHREADS, 1)
void winattn_fused_kernel(const float* __restrict__ x,
                          const float* __restrict__ mask,
                          const float* __restrict__ b_qkv,
                          const float* __restrict__ b_proj,
                          float* __restrict__ out)
{
    extern __shared__ unsigned smu[];

    unsigned* xsu  = smu;                  // 49x196 tf32 bits (phase 1)
    unsigned* attu = smu;                  // 6x49x60 tf32 prob bits (phase 2 overlay)
    unsigned* qsu  = smu + OFF_QS;         // 49x196 q tf32 bits (later O bits)
    unsigned* ksu  = smu + OFF_KS;         // 49x196 k tf32 bits
    unsigned* vtu  = smu + OFF_VT;         // 192x60 v^T tf32 bits

    const int tid  = threadIdx.x;
    const int lane = tid & 31;
    const int w    = tid >> 5;
    const int lg   = lane >> 2;
    const int lr   = lane & 3;
    const int b    = blockIdx.x;
    const float* xg = x + (size_t)b * (NTOK * DIMC);

    // ---------------- load x window as tf32 bits ----------------
    for (int i = tid; i < NTOK * DIMC; i += NTHREADS)
        xsu[(i / DIMC) * XS_STRIDE + (i % DIMC)] = cvt_tf32(xg[i]);
    __syncthreads();

    // ====== phase 1: qkv = x @ w_qkv + b_qkv (TF32 MMA, B streamed from L2) ======
    {
        const int ns = w >> 1;
        const int m0 = (w & 1) * 32;
        const uint2* gw = g_wfrag1 + ns * 6912 + lane;

        float d[2][9][4];
        #pragma unroll
        for (int s = 0; s < 2; s++)
            #pragma unroll
            for (int t = 0; t < 9; t++)
                #pragma unroll
                for (int j = 0; j < 4; j++) d[s][t][j] = 0.0f;

        #pragma unroll 4
        for (int k8 = 0; k8 < 24; ++k8) {
            uint2 bbv[9];
            #pragma unroll
            for (int t = 0; t < 9; t++) bbv[t] = gw[(k8 * 9 + t) * 32];

            const int xc = k8 * 8 + lr;
            unsigned a[2][4];
            #pragma unroll
            for (int s = 0; s < 2; s++) {
                int r0 = m0 + s * 16 + lg;
                a[s][0] = xsu[r0 * XS_STRIDE + xc];
                a[s][1] = xsu[(r0 + 8) * XS_STRIDE + xc];
                a[s][2] = xsu[r0 * XS_STRIDE + xc + 4];
                a[s][3] = xsu[(r0 + 8) * XS_STRIDE + xc + 4];
            }
            #pragma unroll
            for (int t = 0; t < 9; t++) {
                mma_tf32(d[0][t], a[0], (const unsigned*)&bbv[t]);
                mma_tf32(d[1][t], a[1], (const unsigned*)&bbv[t]);
            }
        }
        // epilogue: +bias, scale q; store q,k tf32 bits; v transposed tf32 bits
        #pragma unroll
        for (int s = 0; s < 2; s++) {
            int r0 = m0 + s * 16 + lg, r1 = r0 + 8;
            #pragma unroll
            for (int t = 0; t < 9; t++) {
                int col  = ns * 72 + t * 8 + 2 * lr;
                int part = col / DIMC;
                int cc   = col % DIMC;
                float bv0 = b_qkv[col], bv1 = b_qkv[col + 1];
                if (part == 0) {
                    if (r0 < NTOK) {
                        uint2 o = make_uint2(cvt_tf32((d[s][t][0] + bv0) * QSCALE),
                                             cvt_tf32((d[s][t][1] + bv1) * QSCALE));
                        *(uint2*)&qsu[r0 * QKV_STRIDE + cc] = o;
                    }
                    if (r1 < NTOK) {
                        uint2 o = make_uint2(cvt_tf32((d[s][t][2] + bv0) * QSCALE),
                                             cvt_tf32((d[s][t][3] + bv1) * QSCALE));
                        *(uint2*)&qsu[r1 * QKV_STRIDE + cc] = o;
                    }
                } else if (part == 1) {
                    if (r0 < NTOK) {
                        uint2 o = make_uint2(cvt_tf32(d[s][t][0] + bv0),
                                             cvt_tf32(d[s][t][1] + bv1));
                        *(uint2*)&ksu[r0 * QKV_STRIDE + cc] = o;
                    }
                    if (r1 < NTOK) {
                        uint2 o = make_uint2(cvt_tf32(d[s][t][2] + bv0),
                                             cvt_tf32(d[s][t][3] + bv1));
                        *(uint2*)&ksu[r1 * QKV_STRIDE + cc] = o;
                    }
                } else {
                    if (r0 < NTOK) {
                        vtu[cc * VT_STRIDE + r0]       = cvt_tf32(d[s][t][0] + bv0);
                        vtu[(cc + 1) * VT_STRIDE + r0] = cvt_tf32(d[s][t][1] + bv1);
                    }
                    if (r1 < NTOK) {
                        vtu[cc * VT_STRIDE + r1]       = cvt_tf32(d[s][t][2] + bv0);
                        vtu[(cc + 1) * VT_STRIDE + r1] = cvt_tf32(d[s][t][3] + bv1);
                    }
                }
            }
        }
    }
    // zero-pad v^T token-columns 49..55 (K-padding for 2c must be finite)
    for (int i = tid; i < DIMC * 7; i += NTHREADS)
        vtu[(i / 7) * VT_STRIDE + 49 + (i % 7)] = 0u;
    __syncthreads();   // q/k/vt ready; frees xs region for attu

    // ====== phase 2: attention, fully within-warp (no block syncs) ======
    const float* mrow = mask + (size_t)(b & (NWMASK - 1)) * (NTOK * NTOK);
    unsigned* osu = qsu;
    if (w < 12) {
        const int h  = w >> 1;
        const int m0 = (w & 1) * 32;

        // --- 2a: S = q k^T (TF32 MMA) ---
        float d[2][7][4];
        #pragma unroll
        for (int s = 0; s < 2; s++)
            #pragma unroll
            for (int t = 0; t < 7; t++)
                #pragma unroll
                for (int j = 0; j < 4; j++) d[s][t][j] = 0.0f;

        #pragma unroll
        for (int k8 = 0; k8 < 4; ++k8) {
            const int kb = k8 * 8;
            unsigned a[2][4];
            #pragma unroll
            for (int s = 0; s < 2; s++) {
                int base = (m0 + s * 16 + lg) * QKV_STRIDE + h * HDIM + kb + lr;
                a[s][0] = qsu[base];
                a[s][1] = qsu[base + 8 * QKV_STRIDE];
                a[s][2] = qsu[base + 4];
                a[s][3] = qsu[base + 8 * QKV_STRIDE + 4];
            }
            #pragma unroll
            for (int t = 0; t < 7; t++) {
                unsigned bb[2];
                int base = (t * 8 + lg) * QKV_STRIDE + h * HDIM + kb + lr;
                bb[0] = ksu[base];
                bb[1] = ksu[base + 4];
                mma_tf32(d[0][t], a[0], bb);
                mma_tf32(d[1][t], a[1], bb);
            }
        }

        // --- bias + mask + softmax in registers (quad butterfly) ---
        #pragma unroll
        for (int s = 0; s < 2; s++) {
            #pragma unroll
            for (int half = 0; half < 2; half++) {
                int p = m0 + s * 16 + lg + 8 * half;     // quad-uniform
                float mx = -1e30f;
                if (p < NTOK) {
                    const float* brow = g_bias + (h * NTOK + p) * 56;
                    const float* mr   = mrow + p * NTOK;
                    #pragma unroll
                    for (int t = 0; t < 7; t++) {
                        int q0 = t * 8 + 2 * lr;
                        float2 bv = *(const float2*)&brow[q0];
                        float v0 = -1e30f, v1 = -1e30f;
                        if (q0 < NTOK)
                            v0 = d[s][t][2 * half]     + bv.x + mr[q0];
                        if (q0 + 1 < NTOK)
                            v1 = d[s][t][2 * half + 1] + bv.y + mr[q0 + 1];
                        d[s][t][2 * half]     = v0;
                        d[s][t][2 * half + 1] = v1;
                        mx = fmaxf(mx, fmaxf(v0, v1));
                    }
                }
                mx = fmaxf(mx, __shfl_xor_sync(0xffffffffu, mx, 1));
                mx = fmaxf(mx, __shfl_xor_sync(0xffffffffu, mx, 2));
                float sum = 0.0f;
                if (p < NTOK) {
                    #pragma unroll
                    for (int t = 0; t < 7; t++) {
                        #pragma unroll
                        for (int c = 0; c < 2; c++) {
                            int q = t * 8 + 2 * lr + c;
                            float e = (q < NTOK) ? __expf(d[s][t][2 * half + c] - mx) : 0.0f;
                            d[s][t][2 * half + c] = e;
                            sum += e;
                        }
                    }
                }
                sum += __shfl_xor_sync(0xffffffffu, sum, 1);
                sum += __shfl_xor_sync(0xffffffffu, sum, 2);
                if (p < NTOK) {
                    float inv = 1.0f / sum;
                    unsigned* arow = attu + (h * NTOK + p) * ATT_STRIDE;
                    #pragma unroll
                    for (int t = 0; t < 7; t++) {
                        int q0 = t * 8 + 2 * lr;
                        uint2 bits = make_uint2(0u, 0u);
                        if (q0 < NTOK)     bits.x = cvt_tf32(d[s][t][2 * half] * inv);
                        if (q0 + 1 < NTOK) bits.y = cvt_tf32(d[s][t][2 * half + 1] * inv);
                        *(uint2*)&arow[q0] = bits;
                    }
                }
            }
        }
        __syncwarp();   // same warp re-reads its prob rows in A-frag layout

        // --- 2c: O = P @ V (TF32 MMA); A rows clamped to 48 (garbage rows discarded) ---
        float o[2][4][4];
        #pragma unroll
        for (int s = 0; s < 2; s++)
            #pragma unroll
            for (int t = 0; t < 4; t++)
                #pragma unroll
                for (int j = 0; j < 4; j++) o[s][t][j] = 0.0f;

        int ra[2][2];
        #pragma unroll
        for (int s = 0; s < 2; s++) {
            int r = m0 + s * 16 + lg;
            ra[s][0] = (r < NTOK ? r : 48);
            ra[s][1] = (r + 8 < NTOK ? r + 8 : 48);
        }

        #pragma unroll
        for (int k8 = 0; k8 < 7; ++k8) {
            const int kb = k8 * 8;
            unsigned a[2][4];
            #pragma unroll
            for (int s = 0; s < 2; s++) {
                int b0 = (h * NTOK + ra[s][0]) * ATT_STRIDE + kb + lr;
                int b1 = (h * NTOK + ra[s][1]) * ATT_STRIDE + kb + lr;
                a[s][0] = attu[b0];
                a[s][1] = attu[b1];
                a[s][2] = attu[b0 + 4];
                a[s][3] = attu[b1 + 4];
            }
            #pragma unroll
            for (int t = 0; t < 4; t++) {
                unsigned bb[2];
                int base = (h * HDIM + t * 8 + lg) * VT_STRIDE + kb + lr;
                bb[0] = vtu[base];
                bb[1] = vtu[base + 4];
                mma_tf32(o[0][t], a[0], bb);
                mma_tf32(o[1][t], a[1], bb);
            }
        }
        #pragma unroll
        for (int s = 0; s < 2; s++) {
            int r0 = m0 + s * 16 + lg, r1 = r0 + 8;
            #pragma unroll
            for (int t = 0; t < 4; t++) {
                int dc = h * HDIM + t * 8 + 2 * lr;
                if (r0 < NTOK) {
                    uint2 ov = make_uint2(cvt_tf32(o[s][t][0]), cvt_tf32(o[s][t][1]));
                    *(uint2*)&osu[r0 * QKV_STRIDE + dc] = ov;
                }
                if (r1 < NTOK) {
                    uint2 ov = make_uint2(cvt_tf32(o[s][t][2]), cvt_tf32(o[s][t][3]));
                    *(uint2*)&osu[r1 * QKV_STRIDE + dc] = ov;
                }
            }
        }
    }
    __syncthreads();   // O ready for phase 3

    // ====== phase 3: out = O @ w_proj + b_proj (TF32 MMA, B streamed from L2) ======
    {
        const int ns = w >> 1;
        const int m0 = (w & 1) * 32;
        const uint2* gw = g_wfrag3 + ns * 2304 + lane;

        float d[2][3][4];
        #pragma unroll
        for (int s = 0; s < 2; s++)
            #pragma unroll
            for (int t = 0; t < 3; t++)
                #pragma unroll
                for (int j = 0; j < 4; j++) d[s][t][j] = 0.0f;

        #pragma unroll 4
        for (int k8 = 0; k8 < 24; ++k8) {
            uint2 bbv[3];
            #pragma unroll
            for (int t = 0; t < 3; t++) bbv[t] = gw[(k8 * 3 + t) * 32];

            const int xc = k8 * 8 + lr;
            unsigned a[2][4];
            #pragma unroll
            for (int s = 0; s < 2; s++) {
                int r0 = m0 + s * 16 + lg;
                a[s][0] = qsu[r0 * QKV_STRIDE + xc];
                a[s][1] = qsu[(r0 + 8) * QKV_STRIDE + xc];
                a[s][2] = qsu[r0 * QKV_STRIDE + xc + 4];
                a[s][3] = qsu[(r0 + 8) * QKV_STRIDE + xc + 4];
            }
            #pragma unroll
            for (int t = 0; t < 3; t++) {
                mma_tf32(d[0][t], a[0], (const unsigned*)&bbv[t]);
                mma_tf32(d[1][t], a[1], (const unsigned*)&bbv[t]);
            }
        }
        float* og = out + (size_t)b * (NTOK * DIMC);
        #pragma unroll
        for (int s = 0; s < 2; s++) {
            int r0 = m0 + s * 16 + lg, r1 = r0 + 8;
            #pragma unroll
            for (int t = 0; t < 3; t++) {
                int col = ns * 24 + t * 8 + 2 * lr;
                float bv0 = b_proj[col], bv1 = b_proj[col + 1];
                if (r0 < NTOK) {
                    float2 ov = make_float2(d[s][t][0] + bv0, d[s][t][1] + bv1);
                    *(float2*)&og[r0 * DIMC + col] = ov;
                }
                if (r1 < NTOK) {
                    float2 ov = make_float2(d[s][t][2] + bv0, d[s][t][3] + bv1);
                    *(float2*)&og[r1 * DIMC + col] = ov;
                }
            }
        }
    }
}

extern "C" void kernel_launch(void* const* d_in, const int* in_sizes, int n_in,
                              void* d_out, int out_size)
{
    const float* x      = (const float*)d_in[0];
    const float* mask   = (const float*)d_in[1];
    const float* w_qkv  = (const float*)d_in[2];
    const float* b_qkv  = (const float*)d_in[3];
    const float* w_proj = (const float*)d_in[4];
    const float* b_proj = (const float*)d_in[5];
    const float* table  = (const float*)d_in[6];
    float* out = (float*)d_out;

    prep_kernel<<<148, 256>>>(w_qkv, w_proj, table);

    const int smem_bytes = SMEM_WORDS * (int)sizeof(unsigned);
    cudaFuncSetAttribute(winattn_fused_kernel,
                         cudaFuncAttributeMaxDynamicSharedMemorySize, smem_bytes);

    winattn_fused_kernel<<<BWIN, NTHREADS, smem_bytes>>>(
        x, mask, b_qkv, b_proj, out);
}

// round 8
// speedup vs baseline: 2.9774x; 1.1086x over previous
#include <cuda_runtime.h>
#include <math.h>

#define NTOK   49
#define DIMC   192
#define HEADS  6
#define HDIM   32
#define NWMASK 64
#define QSCALE 0.17677669529663687f
#define NTHREADS 512
#define NCTAS   1024
#define WPC     4

// smem strides (words), conflict-free for the MMA fragment patterns used:
//  stride%32==4  (196): A-LDS bank = 4*lg + lr; ldsm rows 4r+c -> conflict-free
//  stride%32==28 (60): bank = 28*lg + lr; ldsm rows 28r+c -> conflict-free
#define XS_STRIDE  196
#define QKV_STRIDE 196
#define VT_STRIDE  60
#define ATT_STRIDE 60

// smem layout (words). Region0 [0,17640): xs 49x196 (p1) / attu 6x49x60 (p2).
#define OFF_QS 17640
#define OFF_KS 27244
#define OFF_VT 36848
#define OFF_MS 48368                       // mask window 49x49 = 2401 words
#define SMEM_WORDS (48368 + 2401)          // 50769 words = 203,076 B

// ---- precomputed by prep kernel ----
__device__ uint2 g_wfrag1[8 * 24 * 9 * 32];
__device__ uint2 g_wfrag3[8 * 24 * 3 * 32];
__device__ float g_bias[HEADS * NTOK * 56];

__device__ __forceinline__ unsigned cvt_tf32(float f) {
    unsigned r;
    asm("cvt.rna.tf32.f32 %0, %1;" : "=r"(r) : "f"(f));
    return r;
}

__device__ __forceinline__ void mma_tf32(float* d, const unsigned* a, const unsigned* bb) {
    asm volatile(
        "mma.sync.aligned.m16n8k8.row.col.f32.tf32.tf32.f32 "
        "{%0,%1,%2,%3}, {%4,%5,%6,%7}, {%8,%9}, {%0,%1,%2,%3};"
        : "+f"(d[0]), "+f"(d[1]), "+f"(d[2]), "+f"(d[3])
        : "r"(a[0]), "r"(a[1]), "r"(a[2]), "r"(a[3]),
          "r"(bb[0]), "r"(bb[1]));
}

// ldmatrix.x4 over 16B rows: lane gets tf32 A-fragment (a0..a3) of an m16k8 tile
__device__ __forceinline__ void ldsm4(unsigned* r, unsigned addr) {
    asm volatile("ldmatrix.sync.aligned.m8n8.x4.shared.b16 {%0,%1,%2,%3}, [%4];"
                 : "=r"(r[0]), "=r"(r[1]), "=r"(r[2]), "=r"(r[3]) : "r"(addr));
}

__global__ void prep_kernel(const float* __restrict__ w_qkv,
                            const float* __restrict__ w_proj,
                            const float* __restrict__ table)
{
    const int stride = gridDim.x * blockDim.x;
    const int tid0 = blockIdx.x * blockDim.x + threadIdx.x;

    for (int i = tid0; i < 8 * 24 * 9 * 32; i += stride) {
        int lane = i & 31;
        int t    = (i >> 5) % 9;
        int k8   = (i / 288) % 24;
        int ns   = i / 6912;
        int lr = lane & 3, lg = lane >> 2;
        int col = ns * 72 + t * 8 + lg;
        int k0  = k8 * 8 + lr;
        g_wfrag1[i] = make_uint2(cvt_tf32(w_qkv[k0 * 576 + col]),
                                 cvt_tf32(w_qkv[(k0 + 4) * 576 + col]));
    }
    for (int i = tid0; i < 8 * 24 * 3 * 32; i += stride) {
        int lane = i & 31;
        int t    = (i >> 5) % 3;
        int k8   = (i / 96) % 24;
        int ns   = i / 2304;
        int lr = lane & 3, lg = lane >> 2;
        int col = ns * 24 + t * 8 + lg;
        int k0  = k8 * 8 + lr;
        g_wfrag3[i] = make_uint2(cvt_tf32(w_proj[k0 * 192 + col]),
                                 cvt_tf32(w_proj[(k0 + 4) * 192 + col]));
    }
    for (int i = tid0; i < HEADS * NTOK * NTOK; i += stride) {
        int h = i / (NTOK * NTOK);
        int r = i % (NTOK * NTOK);
        int p = r / NTOK, q = r % NTOK;
        int ip = p / 7, jp = p % 7, iq = q / 7, jq = q % 7;
        int ridx = (jp - jq + 6) * 13 + (ip - iq + 6);
        g_bias[(h * NTOK + p) * 56 + q] = table[ridx * HEADS + h];
    }
}

__global__ __launch_bounds__(NTHREADS, 1)
void winattn_fused_kernel(const float* __restrict__ x,
                          const float* __restrict__ mask,
                          const float* __restrict__ b_qkv,
                          const float* __restrict__ b_proj,
                          float* __restrict__ out)
{
    extern __shared__ unsigned smu[];

    unsigned* xsu  = smu;                  // 49x196 tf32 bits (phase 1)
    unsigned* attu = smu;                  // 6x49x60 tf32 prob bits (phase 2 overlay)
    unsigned* qsu  = smu + OFF_QS;
    unsigned* ksu  = smu + OFF_KS;
    unsigned* vtu  = smu + OFF_VT;
    float*    msf  = (float*)(smu + OFF_MS);

    const unsigned sbase = (unsigned)__cvta_generic_to_shared(smu);

    const int tid  = threadIdx.x;
    const int lane = tid & 31;
    const int w    = tid >> 5;
    const int lg   = lane >> 2;
    const int lr   = lane & 3;
    // ldmatrix lane geometry: matrix mi=lane/8 -> (row +8 if mi&1, col +4 if mi>=2)
    const int lrow = (lane & 7) + ((lane >> 3) & 1) * 8;
    const int lcol = (lane >> 4) * 4;

    // ---- preload x of first window (vectorized, tf32 bits) ----
    {
        const float4* xg4 = (const float4*)(x + (size_t)blockIdx.x * WPC * (NTOK * DIMC));
        #pragma unroll
        for (int j = 0; j < 5; j++) {
            int idx = tid + j * NTHREADS;
            if (idx < 2352) {
                float4 v = xg4[idx];
                int row = idx / 48, c4 = idx % 48;
                *(uint4*)&xsu[row * XS_STRIDE + c4 * 4] =
                    make_uint4(cvt_tf32(v.x), cvt_tf32(v.y), cvt_tf32(v.z), cvt_tf32(v.w));
            }
        }
    }
    __syncthreads();

    for (int it = 0; it < WPC; ++it) {
        const int b = blockIdx.x * WPC + it;

        // ====== phase 1: qkv = x @ w_qkv + b_qkv (TF32 MMA, B from L2) ======
        {
            const int ns = w >> 1;
            const int m0 = (w & 1) * 32;
            const uint2* gw = g_wfrag1 + ns * 6912 + lane;

            // mask prefetch (LDG issued early; STS after MMA loop)
            const float* mrow = mask + (size_t)(b & (NWMASK - 1)) * (NTOK * NTOK);
            float mpre[5];
            #pragma unroll
            for (int j = 0; j < 5; j++) {
                int idx = tid + j * NTHREADS;
                if (idx < 2401) mpre[j] = mrow[idx];
            }

            float d[2][9][4];
            #pragma unroll
            for (int s = 0; s < 2; s++)
                #pragma unroll
                for (int t = 0; t < 9; t++)
                    #pragma unroll
                    for (int j = 0; j < 4; j++) d[s][t][j] = 0.0f;

            const unsigned abase = sbase + (((m0 + lrow) * XS_STRIDE + lcol) << 2);
            #pragma unroll 4
            for (int k8 = 0; k8 < 24; ++k8) {
                uint2 bbv[9];
                #pragma unroll
                for (int t = 0; t < 9; t++) bbv[t] = gw[(k8 * 9 + t) * 32];

                unsigned a[2][4];
                ldsm4(a[0], abase + (k8 * 8 << 2));
                ldsm4(a[1], abase + ((16 * XS_STRIDE + k8 * 8) << 2));
                #pragma unroll
                for (int t = 0; t < 9; t++) {
                    mma_tf32(d[0][t], a[0], (const unsigned*)&bbv[t]);
                    mma_tf32(d[1][t], a[1], (const unsigned*)&bbv[t]);
                }
            }
            // epilogue: +bias, scale q; scatter q,k,v^T
            #pragma unroll
            for (int s = 0; s < 2; s++) {
                int r0 = m0 + s * 16 + lg, r1 = r0 + 8;
                #pragma unroll
                for (int t = 0; t < 9; t++) {
                    int col  = ns * 72 + t * 8 + 2 * lr;
                    int part = col / DIMC;
                    int cc   = col % DIMC;
                    float bv0 = b_qkv[col], bv1 = b_qkv[col + 1];
                    if (part == 0) {
                        if (r0 < NTOK)
                            *(uint2*)&qsu[r0 * QKV_STRIDE + cc] =
                                make_uint2(cvt_tf32((d[s][t][0] + bv0) * QSCALE),
                                           cvt_tf32((d[s][t][1] + bv1) * QSCALE));
                        if (r1 < NTOK)
                            *(uint2*)&qsu[r1 * QKV_STRIDE + cc] =
                                make_uint2(cvt_tf32((d[s][t][2] + bv0) * QSCALE),
                                           cvt_tf32((d[s][t][3] + bv1) * QSCALE));
                    } else if (part == 1) {
                        if (r0 < NTOK)
                            *(uint2*)&ksu[r0 * QKV_STRIDE + cc] =
                                make_uint2(cvt_tf32(d[s][t][0] + bv0),
                                           cvt_tf32(d[s][t][1] + bv1));
                        if (r1 < NTOK)
                            *(uint2*)&ksu[r1 * QKV_STRIDE + cc] =
                                make_uint2(cvt_tf32(d[s][t][2] + bv0),
                                           cvt_tf32(d[s][t][3] + bv1));
                    } else {
                        if (r0 < NTOK) {
                            vtu[cc * VT_STRIDE + r0]       = cvt_tf32(d[s][t][0] + bv0);
                            vtu[(cc + 1) * VT_STRIDE + r0] = cvt_tf32(d[s][t][1] + bv1);
                        }
                        if (r1 < NTOK) {
                            vtu[cc * VT_STRIDE + r1]       = cvt_tf32(d[s][t][2] + bv0);
                            vtu[(cc + 1) * VT_STRIDE + r1] = cvt_tf32(d[s][t][3] + bv1);
                        }
                    }
                }
            }
            // mask -> smem
            #pragma unroll
            for (int j = 0; j < 5; j++) {
                int idx = tid + j * NTHREADS;
                if (idx < 2401) msf[idx] = mpre[j];
            }
        }
        // zero-pad v^T token-columns 49..55
        for (int i = tid; i < DIMC * 7; i += NTHREADS)
            vtu[(i / 7) * VT_STRIDE + 49 + (i % 7)] = 0u;
        __syncthreads();

        // ====== phase 2: attention (12 warps, within-warp only) ======
        if (w < 12) {
            const int h  = w >> 1;
            const int m0 = (w & 1) * 32;

            float d[2][7][4];
            #pragma unroll
            for (int s = 0; s < 2; s++)
                #pragma unroll
                for (int t = 0; t < 7; t++)
                    #pragma unroll
                    for (int j = 0; j < 4; j++) d[s][t][j] = 0.0f;

            const unsigned qab = sbase +
                ((OFF_QS + (m0 + lrow) * QKV_STRIDE + h * HDIM + lcol) << 2);
            #pragma unroll
            for (int k8 = 0; k8 < 4; ++k8) {
                const int kb = k8 * 8;
                unsigned a[2][4];
                ldsm4(a[0], qab + (kb << 2));
                ldsm4(a[1], qab + ((16 * QKV_STRIDE + kb) << 2));
                #pragma unroll
                for (int t = 0; t < 7; t++) {
                    unsigned bb[2];
                    int base = (t * 8 + lg) * QKV_STRIDE + h * HDIM + kb + lr;
                    bb[0] = ksu[base];
                    bb[1] = ksu[base + 4];
                    mma_tf32(d[0][t], a[0], bb);
                    mma_tf32(d[1][t], a[1], bb);
                }
            }

            // bias + mask + softmax in registers (quad butterfly)
            #pragma unroll
            for (int s = 0; s < 2; s++) {
                #pragma unroll
                for (int half = 0; half < 2; half++) {
                    int p = m0 + s * 16 + lg + 8 * half;
                    float mx = -1e30f;
                    if (p < NTOK) {
                        const float* brow = g_bias + (h * NTOK + p) * 56;
                        const float* mr   = msf + p * NTOK;
                        #pragma unroll
                        for (int t = 0; t < 7; t++) {
                            int q0 = t * 8 + 2 * lr;
                            float2 bv = *(const float2*)&brow[q0];
                            float v0 = -1e30f, v1 = -1e30f;
                            if (q0 < NTOK)     v0 = d[s][t][2 * half]     + bv.x + mr[q0];
                            if (q0 + 1 < NTOK) v1 = d[s][t][2 * half + 1] + bv.y + mr[q0 + 1];
                            d[s][t][2 * half]     = v0;
                            d[s][t][2 * half + 1] = v1;
                            mx = fmaxf(mx, fmaxf(v0, v1));
                        }
                    }
                    mx = fmaxf(mx, __shfl_xor_sync(0xffffffffu, mx, 1));
                    mx = fmaxf(mx, __shfl_xor_sync(0xffffffffu, mx, 2));
                    float sum = 0.0f;
                    if (p < NTOK) {
                        #pragma unroll
                        for (int t = 0; t < 7; t++) {
                            #pragma unroll
                            for (int c = 0; c < 2; c++) {
                                int q = t * 8 + 2 * lr + c;
                                float e = (q < NTOK) ? __expf(d[s][t][2 * half + c] - mx) : 0.0f;
                                d[s][t][2 * half + c] = e;
                                sum += e;
                            }
                        }
                    }
                    sum += __shfl_xor_sync(0xffffffffu, sum, 1);
                    sum += __shfl_xor_sync(0xffffffffu, sum, 2);
                    if (p < NTOK) {
                        float inv = 1.0f / sum;
                        unsigned* arow = attu + (h * NTOK + p) * ATT_STRIDE;
                        #pragma unroll
                        for (int t = 0; t < 7; t++) {
                            int q0 = t * 8 + 2 * lr;
                            uint2 bits = make_uint2(0u, 0u);
                            if (q0 < NTOK)     bits.x = cvt_tf32(d[s][t][2 * half] * inv);
                            if (q0 + 1 < NTOK) bits.y = cvt_tf32(d[s][t][2 * half + 1] * inv);
                            *(uint2*)&arow[q0] = bits;
                        }
                    }
                }
            }
            __syncwarp();

            // 2c: O = P @ V; overflow A rows read adjacent smem (finite, discarded)
            float o[2][4][4];
            #pragma unroll
            for (int s = 0; s < 2; s++)
                #pragma unroll
                for (int t = 0; t < 4; t++)
                    #pragma unroll
                    for (int j = 0; j < 4; j++) o[s][t][j] = 0.0f;

            const unsigned aab = sbase +
                (((h * NTOK + m0 + lrow) * ATT_STRIDE + lcol) << 2);
            #pragma unroll
            for (int k8 = 0; k8 < 7; ++k8) {
                const int kb = k8 * 8;
                unsigned a[2][4];
                ldsm4(a[0], aab + (kb << 2));
                ldsm4(a[1], aab + ((16 * ATT_STRIDE + kb) << 2));
                #pragma unroll
                for (int t = 0; t < 4; t++) {
                    unsigned bb[2];
                    int base = (h * HDIM + t * 8 + lg) * VT_STRIDE + kb + lr;
                    bb[0] = vtu[base];
                    bb[1] = vtu[base + 4];
                    mma_tf32(o[0][t], a[0], bb);
                    mma_tf32(o[1][t], a[1], bb);
                }
            }
            unsigned* osu = qsu;
            #pragma unroll
            for (int s = 0; s < 2; s++) {
                int r0 = m0 + s * 16 + lg, r1 = r0 + 8;
                #pragma unroll
                for (int t = 0; t < 4; t++) {
                    int dc = h * HDIM + t * 8 + 2 * lr;
                    if (r0 < NTOK)
                        *(uint2*)&osu[r0 * QKV_STRIDE + dc] =
                            make_uint2(cvt_tf32(o[s][t][0]), cvt_tf32(o[s][t][1]));
                    if (r1 < NTOK)
                        *(uint2*)&osu[r1 * QKV_STRIDE + dc] =
                            make_uint2(cvt_tf32(o[s][t][2]), cvt_tf32(o[s][t][3]));
                }
            }
        }
        __syncthreads();   // O ready; attu/xs region dead

        // ---- prefetch next window's x (overlaps phase 3) ----
        const bool havex = (it + 1 < WPC);
        float4 xpre[5];
        if (havex) {
            const float4* xg4 = (const float4*)(x + (size_t)(b + 1) * (NTOK * DIMC));
            #pragma unroll
            for (int j = 0; j < 5; j++) {
                int idx = tid + j * NTHREADS;
                if (idx < 2352) xpre[j] = xg4[idx];
            }
        }

        // ====== phase 3: out = O @ w_proj + b_proj (TF32 MMA, B from L2) ======
        {
            const int ns = w >> 1;
            const int m0 = (w & 1) * 32;
            const uint2* gw = g_wfrag3 + ns * 2304 + lane;

            float d[2][3][4];
            #pragma unroll
            for (int s = 0; s < 2; s++)
                #pragma unroll
                for (int t = 0; t < 3; t++)
                    #pragma unroll
                    for (int j = 0; j < 4; j++) d[s][t][j] = 0.0f;

            const unsigned oab = sbase +
                ((OFF_QS + (m0 + lrow) * QKV_STRIDE + lcol) << 2);
            #pragma unroll 4
            for (int k8 = 0; k8 < 24; ++k8) {
                uint2 bbv[3];
                #pragma unroll
                for (int t = 0; t < 3; t++) bbv[t] = gw[(k8 * 3 + t) * 32];

                unsigned a[2][4];
                ldsm4(a[0], oab + (k8 * 8 << 2));
                ldsm4(a[1], oab + ((16 * QKV_STRIDE + k8 * 8) << 2));
                #pragma unroll
                for (int t = 0; t < 3; t++) {
                    mma_tf32(d[0][t], a[0], (const unsigned*)&bbv[t]);
                    mma_tf32(d[1][t], a[1], (const unsigned*)&bbv[t]);
                }
            }
            float* og = out + (size_t)b * (NTOK * DIMC);
            #pragma unroll
            for (int s = 0; s < 2; s++) {
                int r0 = m0 + s * 16 + lg, r1 = r0 + 8;
                #pragma unroll
                for (int t = 0; t < 3; t++) {
                    int col = ns * 24 + t * 8 + 2 * lr;
                    float bv0 = b_proj[col], bv1 = b_proj[col + 1];
                    if (r0 < NTOK)
                        *(float2*)&og[r0 * DIMC + col] =
                            make_float2(d[s][t][0] + bv0, d[s][t][1] + bv1);
                    if (r1 < NTOK)
                        *(float2*)&og[r1 * DIMC + col] =
                            make_float2(d[s][t][2] + bv0, d[s][t][3] + bv1);
                }
            }
        }

        // ---- store prefetched x for next window ----
        if (havex) {
            #pragma unroll
            for (int j = 0; j < 5; j++) {
                int idx = tid + j * NTHREADS;
                if (idx < 2352) {
                    int row = idx / 48, c4 = idx % 48;
                    *(uint4*)&xsu[row * XS_STRIDE + c4 * 4] =
                        make_uint4(cvt_tf32(xpre[j].x), cvt_tf32(xpre[j].y),
                                   cvt_tf32(xpre[j].z), cvt_tf32(xpre[j].w));
                }
            }
        }
        __syncthreads();
    }
}

extern "C" void kernel_launch(void* const* d_in, const int* in_sizes, int n_in,
                              void* d_out, int out_size)
{
    const float* x      = (const float*)d_in[0];
    const float* mask   = (const float*)d_in[1];
    const float* w_qkv  = (const float*)d_in[2];
    const float* b_qkv  = (const float*)d_in[3];
    const float* w_proj = (const float*)d_in[4];
    const float* b_proj = (const float*)d_in[5];
    const float* table  = (const float*)d_in[6];
    float* out = (float*)d_out;

    prep_kernel<<<148, 256>>>(w_qkv, w_proj, table);

    const int smem_bytes = SMEM_WORDS * (int)sizeof(unsigned);
    cudaFuncSetAttribute(winattn_fused_kernel,
                         cudaFuncAttributeMaxDynamicSharedMemorySize, smem_bytes);

    winattn_fused_kernel<<<NCTAS, NTHREADS, smem_bytes>>>(
        x, mask, b_qkv, b_proj, out);
}

// round 9
// speedup vs baseline: 3.1638x; 1.0626x over previous
#include <cuda_runtime.h>
#include <math.h>

#define NTOK   49
#define DIMC   192
#define HEADS  6
#define HDIM   32
#define NWMASK 64
#define QSCALE 0.17677669529663687f
#define NTHREADS 512
#define NCTAS   1024
#define WPC     4

#define XS_STRIDE  196
#define QKV_STRIDE 196
#define VT_STRIDE  60
#define ATT_STRIDE 60

#define OFF_QS 17640
#define OFF_KS 27244
#define OFF_VT 36848
#define SMEM_WORDS (36848 + 192 * 60)      // 48368 words = 193,472 B

__device__ uint2 g_wfrag1[8 * 24 * 9 * 32];        // q-cols pre-scaled by QSCALE
__device__ uint2 g_wfrag3[8 * 24 * 3 * 32];
__device__ float g_bq[576];                         // bias, q-part pre-scaled
__device__ float g_cmb[NWMASK * HEADS * NTOK * 56]; // bias+mask combined

__device__ __forceinline__ unsigned cvt_tf32(float f) {
    unsigned r;
    asm("cvt.rna.tf32.f32 %0, %1;" : "=r"(r) : "f"(f));
    return r;
}

__device__ __forceinline__ void mma_tf32(float* d, const unsigned* a, const unsigned* bb) {
    asm volatile(
        "mma.sync.aligned.m16n8k8.row.col.f32.tf32.tf32.f32 "
        "{%0,%1,%2,%3}, {%4,%5,%6,%7}, {%8,%9}, {%0,%1,%2,%3};"
        : "+f"(d[0]), "+f"(d[1]), "+f"(d[2]), "+f"(d[3])
        : "r"(a[0]), "r"(a[1]), "r"(a[2]), "r"(a[3]),
          "r"(bb[0]), "r"(bb[1]));
}

__device__ __forceinline__ void ldsm4(unsigned* r, unsigned addr) {
    asm volatile("ldmatrix.sync.aligned.m8n8.x4.shared.b16 {%0,%1,%2,%3}, [%4];"
                 : "=r"(r[0]), "=r"(r[1]), "=r"(r[2]), "=r"(r[3]) : "r"(addr));
}

__global__ void prep_kernel(const float* __restrict__ w_qkv,
                            const float* __restrict__ w_proj,
                            const float* __restrict__ table,
                            const float* __restrict__ mask,
                            const float* __restrict__ b_qkv)
{
    const int stride = gridDim.x * blockDim.x;
    const int tid0 = blockIdx.x * blockDim.x + threadIdx.x;

    for (int i = tid0; i < 8 * 24 * 9 * 32; i += stride) {
        int lane = i & 31;
        int t    = (i >> 5) % 9;
        int k8   = (i / 288) % 24;
        int ns   = i / 6912;
        int lr = lane & 3, lg = lane >> 2;
        int col = ns * 72 + t * 8 + lg;
        int k0  = k8 * 8 + lr;
        float sc = (col < DIMC) ? QSCALE : 1.0f;
        g_wfrag1[i] = make_uint2(cvt_tf32(w_qkv[k0 * 576 + col] * sc),
                                 cvt_tf32(w_qkv[(k0 + 4) * 576 + col] * sc));
    }
    for (int i = tid0; i < 8 * 24 * 3 * 32; i += stride) {
        int lane = i & 31;
        int t    = (i >> 5) % 3;
        int k8   = (i / 96) % 24;
        int ns   = i / 2304;
        int lr = lane & 3, lg = lane >> 2;
        int col = ns * 24 + t * 8 + lg;
        int k0  = k8 * 8 + lr;
        g_wfrag3[i] = make_uint2(cvt_tf32(w_proj[k0 * 192 + col]),
                                 cvt_tf32(w_proj[(k0 + 4) * 192 + col]));
    }
    for (int i = tid0; i < 576; i += stride)
        g_bq[i] = b_qkv[i] * (i < DIMC ? QSCALE : 1.0f);

    for (int i = tid0; i < NWMASK * HEADS * NTOK * NTOK; i += stride) {
        int wm = i / (HEADS * NTOK * NTOK);
        int r  = i % (HEADS * NTOK * NTOK);
        int h  = r / (NTOK * NTOK);
        int r2 = r % (NTOK * NTOK);
        int p = r2 / NTOK, q = r2 % NTOK;
        int ip = p / 7, jp = p % 7, iq = q / 7, jq = q % 7;
        int ridx = (jp - jq + 6) * 13 + (ip - iq + 6);
        g_cmb[((wm * HEADS + h) * NTOK + p) * 56 + q] =
            mask[wm * (NTOK * NTOK) + p * NTOK + q] + table[ridx * HEADS + h];
    }
}

__global__ __launch_bounds__(NTHREADS, 1)
void winattn_fused_kernel(const float* __restrict__ x,
                          const float* __restrict__ b_proj,
                          float* __restrict__ out)
{
    extern __shared__ unsigned smu[];

    unsigned* xsu  = smu;
    unsigned* attu = smu;
    unsigned* qsu  = smu + OFF_QS;
    unsigned* ksu  = smu + OFF_KS;
    unsigned* vtu  = smu + OFF_VT;

    const unsigned sbase = (unsigned)__cvta_generic_to_shared(smu);

    const int tid  = threadIdx.x;
    const int lane = tid & 31;
    const int w    = tid >> 5;
    const int lg   = lane >> 2;
    const int lr   = lane & 3;
    const int lrow = (lane & 7) + ((lane >> 3) & 1) * 8;
    const int lcol = (lane >> 4) * 4;

    {
        const float4* xg4 = (const float4*)(x + (size_t)blockIdx.x * WPC * (NTOK * DIMC));
        #pragma unroll
        for (int j = 0; j < 5; j++) {
            int idx = tid + j * NTHREADS;
            if (idx < 2352) {
                float4 v = xg4[idx];
                int row = idx / 48, c4 = idx % 48;
                *(uint4*)&xsu[row * XS_STRIDE + c4 * 4] =
                    make_uint4(cvt_tf32(v.x), cvt_tf32(v.y), cvt_tf32(v.z), cvt_tf32(v.w));
            }
        }
        for (int i = tid; i < DIMC * 7; i += NTHREADS)
            vtu[(i / 7) * VT_STRIDE + 49 + (i % 7)] = 0u;
    }
    __syncthreads();

    for (int it = 0; it < WPC; ++it) {
        const int b = blockIdx.x * WPC + it;

        // ====== phase 1 ======
        {
            const int ns = w >> 1;
            const int m0 = (w & 1) * 32;
            const uint2* gw = g_wfrag1 + ns * 6912 + lane;

            float d[2][9][4];
            #pragma unroll
            for (int s = 0; s < 2; s++)
                #pragma unroll
                for (int t = 0; t < 9; t++)
                    #pragma unroll
                    for (int j = 0; j < 4; j++) d[s][t][j] = 0.0f;

            const unsigned abase = sbase + (((m0 + lrow) * XS_STRIDE + lcol) << 2);
            #pragma unroll 4
            for (int k8 = 0; k8 < 24; ++k8) {
                uint2 bbv[9];
                #pragma unroll
                for (int t = 0; t < 9; t++) bbv[t] = gw[(k8 * 9 + t) * 32];

                unsigned a[2][4];
                ldsm4(a[0], abase + (k8 * 8 << 2));
                ldsm4(a[1], abase + ((16 * XS_STRIDE + k8 * 8) << 2));
                #pragma unroll
                for (int t = 0; t < 9; t++) {
                    mma_tf32(d[0][t], a[0], (const unsigned*)&bbv[t]);
                    mma_tf32(d[1][t], a[1], (const unsigned*)&bbv[t]);
                }
            }
            #pragma unroll
            for (int s = 0; s < 2; s++) {
                int r0 = m0 + s * 16 + lg, r1 = r0 + 8;
                #pragma unroll
                for (int t = 0; t < 9; t++) {
                    int col  = ns * 72 + t * 8 + 2 * lr;
                    int part = col / DIMC;
                    int cc   = col % DIMC;
                    float2 bq = *(const float2*)&g_bq[col];
                    if (part == 0) {
                        if (r0 < NTOK)
                            *(uint2*)&qsu[r0 * QKV_STRIDE + cc] =
                                make_uint2(cvt_tf32(d[s][t][0] + bq.x),
                                           cvt_tf32(d[s][t][1] + bq.y));
                        if (r1 < NTOK)
                            *(uint2*)&qsu[r1 * QKV_STRIDE + cc] =
                                make_uint2(cvt_tf32(d[s][t][2] + bq.x),
                                           cvt_tf32(d[s][t][3] + bq.y));
                    } else if (part == 1) {
                        if (r0 < NTOK)
                            *(uint2*)&ksu[r0 * QKV_STRIDE + cc] =
                                make_uint2(cvt_tf32(d[s][t][0] + bq.x),
                                           cvt_tf32(d[s][t][1] + bq.y));
                        if (r1 < NTOK)
                            *(uint2*)&ksu[r1 * QKV_STRIDE + cc] =
                                make_uint2(cvt_tf32(d[s][t][2] + bq.x),
                                           cvt_tf32(d[s][t][3] + bq.y));
                    } else {
                        if (r0 < NTOK) {
                            vtu[cc * VT_STRIDE + r0]       = cvt_tf32(d[s][t][0] + bq.x);
                            vtu[(cc + 1) * VT_STRIDE + r0] = cvt_tf32(d[s][t][1] + bq.y);
                        }
                        if (r1 < NTOK) {
                            vtu[cc * VT_STRIDE + r1]       = cvt_tf32(d[s][t][2] + bq.x);
                            vtu[(cc + 1) * VT_STRIDE + r1] = cvt_tf32(d[s][t][3] + bq.y);
                        }
                    }
                }
            }
        }
        __syncthreads();

        // ====== phase 2: 24 units over 16 warps ======
        {
            const int wm = b & (NWMASK - 1);
            for (int ui = w; ui < 24; ui += 16) {
                const int h  = ui >> 2;
                const int m0 = (ui & 3) * 16;

                float2 cmb[2][7];
                #pragma unroll
                for (int half = 0; half < 2; half++) {
                    int p = m0 + lg + 8 * half;
                    int pc = (p < NTOK) ? p : (NTOK - 1);
                    const float2* crow =
                        (const float2*)&g_cmb[((wm * HEADS + h) * NTOK + pc) * 56];
                    #pragma unroll
                    for (int t = 0; t < 7; t++)
                        cmb[half][t] = crow[(t * 8 + 2 * lr) >> 1];
                }

                float d[7][4];
                #pragma unroll
                for (int t = 0; t < 7; t++)
                    #pragma unroll
                    for (int j = 0; j < 4; j++) d[t][j] = 0.0f;

                const unsigned qab = sbase +
                    ((OFF_QS + (m0 + lrow) * QKV_STRIDE + h * HDIM + lcol) << 2);
                #pragma unroll
                for (int k8 = 0; k8 < 4; ++k8) {
                    unsigned a[4];
                    ldsm4(a, qab + (k8 * 8 << 2));
                    #pragma unroll
                    for (int t = 0; t < 7; t++) {
                        unsigned bb[2];
                        int base = (t * 8 + lg) * QKV_STRIDE + h * HDIM + k8 * 8 + lr;
                        bb[0] = ksu[base];
                        bb[1] = ksu[base + 4];
                        mma_tf32(d[t], a, bb);
                    }
                }

                float inv2[2];
                #pragma unroll
                for (int half = 0; half < 2; half++) {
                    int p = m0 + lg + 8 * half;
                    float mx = -1e30f;
                    if (p < NTOK) {
                        #pragma unroll
                        for (int t = 0; t < 7; t++) {
                            int q0 = t * 8 + 2 * lr;
                            float v0 = -1e30f, v1 = -1e30f;
                            if (q0 < NTOK)     v0 = d[t][2 * half]     + cmb[half][t].x;
                            if (q0 + 1 < NTOK) v1 = d[t][2 * half + 1] + cmb[half][t].y;
                            d[t][2 * half]     = v0;
                            d[t][2 * half + 1] = v1;
                            mx = fmaxf(mx, fmaxf(v0, v1));
                        }
                    }
                    mx = fmaxf(mx, __shfl_xor_sync(0xffffffffu, mx, 1));
                    mx = fmaxf(mx, __shfl_xor_sync(0xffffffffu, mx, 2));
                    float sum = 0.0f;
                    if (p < NTOK) {
                        #pragma unroll
                        for (int t = 0; t < 7; t++) {
                            #pragma unroll
                            for (int c = 0; c < 2; c++) {
                                int q = t * 8 + 2 * lr + c;
                                float e = (q < NTOK) ? __expf(d[t][2 * half + c] - mx) : 0.0f;
                                d[t][2 * half + c] = e;
                                sum += e;
                            }
                        }
                        unsigned* arow = attu + (h * NTOK + p) * ATT_STRIDE;
                        #pragma unroll
                        for (int t = 0; t < 7; t++) {
                            int q0 = t * 8 + 2 * lr;
                            uint2 bits = make_uint2(0u, 0u);
                            if (q0 < NTOK)     bits.x = cvt_tf32(d[t][2 * half]);
                            if (q0 + 1 < NTOK) bits.y = cvt_tf32(d[t][2 * half + 1]);
                            *(uint2*)&arow[q0] = bits;
                        }
                    }
                    sum += __shfl_xor_sync(0xffffffffu, sum, 1);
                    sum += __shfl_xor_sync(0xffffffffu, sum, 2);
                    inv2[half] = 1.0f / sum;
                }
                __syncwarp();

                float o[4][4];
                #pragma unroll
                for (int t = 0; t < 4; t++)
                    #pragma unroll
                    for (int j = 0; j < 4; j++) o[t][j] = 0.0f;

                const unsigned aab = sbase +
                    (((h * NTOK + m0 + lrow) * ATT_STRIDE + lcol) << 2);
                #pragma unroll
                for (int k8 = 0; k8 < 7; ++k8) {
                    unsigned a[4];
                    ldsm4(a, aab + (k8 * 8 << 2));
                    #pragma unroll
                    for (int t = 0; t < 4; t++) {
                        unsigned bb[2];
                        int base = (h * HDIM + t * 8 + lg) * VT_STRIDE + k8 * 8 + lr;
                        bb[0] = vtu[base];
                        bb[1] = vtu[base + 4];
                        mma_tf32(o[t], a, bb);
                    }
                }
                int r0 = m0 + lg, r1 = r0 + 8;
                #pragma unroll
                for (int t = 0; t < 4; t++) {
                    int dc = h * HDIM + t * 8 + 2 * lr;
                    if (r0 < NTOK)
                        *(uint2*)&qsu[r0 * QKV_STRIDE + dc] =
                            make_uint2(cvt_tf32(o[t][0] * inv2[0]),
                                       cvt_tf32(o[t][1] * inv2[0]));
                    if (r1 < NTOK)
                        *(uint2*)&qsu[r1 * QKV_STRIDE + dc] =
                            make_uint2(cvt_tf32(o[t][2] * inv2[1]),
                                       cvt_tf32(o[t][3] * inv2[1]));
                }
            }
        }
        __syncthreads();

        const bool havex = (it + 1 < WPC);
        float4 xpre[5];
        if (havex) {
            const float4* xg4 = (const float4*)(x + (size_t)(b + 1) * (NTOK * DIMC));
            #pragma unroll
            for (int j = 0; j < 5; j++) {
                int idx = tid + j * NTHREADS;
                if (idx < 2352) xpre[j] = xg4[idx];
            }
        }

        // ====== phase 3 ======
        {
            const int ns = w >> 1;
            const int m0 = (w & 1) * 32;
            const uint2* gw = g_wfrag3 + ns * 2304 + lane;

            float d[2][3][4];
            #pragma unroll
            for (int s = 0; s < 2; s++)
                #pragma unroll
                for (int t = 0; t < 3; t++)
                    #pragma unroll
                    for (int j = 0; j < 4; j++) d[s][t][j] = 0.0f;

            const unsigned oab = sbase +
                ((OFF_QS + (m0 + lrow) * QKV_STRIDE + lcol) << 2);
            #pragma unroll 4
            for (int k8 = 0; k8 < 24; ++k8) {
                uint2 bbv[3];
                #pragma unroll
                for (int t = 0; t < 3; t++) bbv[t] = gw[(k8 * 3 + t) * 32];

                unsigned a[2][4];
                ldsm4(a[0], oab + (k8 * 8 << 2));
                ldsm4(a[1], oab + ((16 * QKV_STRIDE + k8 * 8) << 2));
                #pragma unroll
                for (int t = 0; t < 3; t++) {
                    mma_tf32(d[0][t], a[0], (const unsigned*)&bbv[t]);
                    mma_tf32(d[1][t], a[1], (const unsigned*)&bbv[t]);
                }
            }
            float* og = out + (size_t)b * (NTOK * DIMC);
            #pragma unroll
            for (int s = 0; s < 2; s++) {
                int r0 = m0 + s * 16 + lg, r1 = r0 + 8;
                #pragma unroll
                for (int t = 0; t < 3; t++) {
                    int col = ns * 24 + t * 8 + 2 * lr;
                    float2 bv = *(const float2*)&b_proj[col];
                    if (r0 < NTOK)
                        *(float2*)&og[r0 * DIMC + col] =
                            make_float2(d[s][t][0] + bv.x, d[s][t][1] + bv.y);
                    if (r1 < NTOK)
                        *(float2*)&og[r1 * DIMC + col] =
                            make_float2(d[s][t][2] + bv.x, d[s][t][3] + bv.y);
                }
            }
        }

        if (havex) {
            #pragma unroll
            for (int j = 0; j < 5; j++) {
                int idx = tid + j * NTHREADS;
                if (idx < 2352) {
                    int row = idx / 48, c4 = idx % 48;
                    *(uint4*)&xsu[row * XS_STRIDE + c4 * 4] =
                        make_uint4(cvt_tf32(xpre[j].x), cvt_tf32(xpre[j].y),
                                   cvt_tf32(xpre[j].z), cvt_tf32(xpre[j].w));
                }
            }
        }
        __syncthreads();
    }
}

extern "C" void kernel_launch(void* const* d_in, const int* in_sizes, int n_in,
                              void* d_out, int out_size)
{
    const float* x      = (const float*)d_in[0];
    const float* mask   = (const float*)d_in[1];
    const float* w_qkv  = (const float*)d_in[2];
    const float* b_qkv  = (const float*)d_in[3];
    const float* w_proj = (const float*)d_in[4];
    const float* b_proj = (const float*)d_in[5];
    const float* table  = (const float*)d_in[6];
    float* out = (float*)d_out;

    prep_kernel<<<148, 256>>>(w_qkv, w_proj, table, mask, b_qkv);

    const int smem_bytes = SMEM_WORDS * (int)sizeof(unsigned);
    cudaFuncSetAttribute(winattn_fused_kernel,
                         cudaFuncAttributeMaxDynamicSharedMemorySize, smem_bytes);

    winattn_fused_kernel<<<NCTAS, NTHREADS, smem_bytes>>>(x, b_proj, out);
}

// round 10
// speedup vs baseline: 3.1852x; 1.0068x over previous
#include <cuda_runtime.h>
#include <math.h>

#define NTOK   49
#define DIMC   192
#define HEADS  6
#define HDIM   32
#define NWMASK 64
#define QSCALE 0.17677669529663687f
#define NTHREADS 512
#define NCTAS   1024
#define WPC     4

#define XS_STRIDE  196
#define QKV_STRIDE 196
#define VT_STRIDE  60
#define ATT_STRIDE 60

#define OFF_QS 17640
#define OFF_KS 27244
#define OFF_VT 36848
#define SMEM_WORDS (36848 + 192 * 60)      // 48368 words = 193,472 B

__device__ uint2 g_wfrag1[8 * 24 * 9 * 32];        // q-cols pre-scaled by QSCALE
__device__ uint2 g_wfrag3[8 * 24 * 3 * 32];
__device__ float g_bq[576];                         // bias, q-part pre-scaled
__device__ float g_cmb[NWMASK * HEADS * NTOK * 56]; // bias+mask combined

__device__ __forceinline__ unsigned cvt_tf32(float f) {
    unsigned r;
    asm("cvt.rna.tf32.f32 %0, %1;" : "=r"(r) : "f"(f));
    return r;
}

__device__ __forceinline__ void mma_tf32(float* d, const unsigned* a, const unsigned* bb) {
    asm volatile(
        "mma.sync.aligned.m16n8k8.row.col.f32.tf32.tf32.f32 "
        "{%0,%1,%2,%3}, {%4,%5,%6,%7}, {%8,%9}, {%0,%1,%2,%3};"
        : "+f"(d[0]), "+f"(d[1]), "+f"(d[2]), "+f"(d[3])
        : "r"(a[0]), "r"(a[1]), "r"(a[2]), "r"(a[3]),
          "r"(bb[0]), "r"(bb[1]));
}

__device__ __forceinline__ void ldsm4(unsigned* r, unsigned addr) {
    asm volatile("ldmatrix.sync.aligned.m8n8.x4.shared.b16 {%0,%1,%2,%3}, [%4];"
                 : "=r"(r[0]), "=r"(r[1]), "=r"(r[2]), "=r"(r[3]) : "r"(addr));
}

__device__ __forceinline__ void ldsm2(unsigned* r, unsigned addr) {
    asm volatile("ldmatrix.sync.aligned.m8n8.x2.shared.b16 {%0,%1}, [%2];"
                 : "=r"(r[0]), "=r"(r[1]) : "r"(addr));
}

__global__ void prep_kernel(const float* __restrict__ w_qkv,
                            const float* __restrict__ w_proj,
                            const float* __restrict__ table,
                            const float* __restrict__ mask,
                            const float* __restrict__ b_qkv)
{
    const int stride = gridDim.x * blockDim.x;
    const int tid0 = blockIdx.x * blockDim.x + threadIdx.x;

    for (int i = tid0; i < 8 * 24 * 9 * 32; i += stride) {
        int lane = i & 31;
        int t    = (i >> 5) % 9;
        int k8   = (i / 288) % 24;
        int ns   = i / 6912;
        int lr = lane & 3, lg = lane >> 2;
        int col = ns * 72 + t * 8 + lg;
        int k0  = k8 * 8 + lr;
        float sc = (col < DIMC) ? QSCALE : 1.0f;
        g_wfrag1[i] = make_uint2(cvt_tf32(w_qkv[k0 * 576 + col] * sc),
                                 cvt_tf32(w_qkv[(k0 + 4) * 576 + col] * sc));
    }
    for (int i = tid0; i < 8 * 24 * 3 * 32; i += stride) {
        int lane = i & 31;
        int t    = (i >> 5) % 3;
        int k8   = (i / 96) % 24;
        int ns   = i / 2304;
        int lr = lane & 3, lg = lane >> 2;
        int col = ns * 24 + t * 8 + lg;
        int k0  = k8 * 8 + lr;
        g_wfrag3[i] = make_uint2(cvt_tf32(w_proj[k0 * 192 + col]),
                                 cvt_tf32(w_proj[(k0 + 4) * 192 + col]));
    }
    for (int i = tid0; i < 576; i += stride)
        g_bq[i] = b_qkv[i] * (i < DIMC ? QSCALE : 1.0f);

    for (int i = tid0; i < NWMASK * HEADS * NTOK * NTOK; i += stride) {
        int wm = i / (HEADS * NTOK * NTOK);
        int r  = i % (HEADS * NTOK * NTOK);
        int h  = r / (NTOK * NTOK);
        int r2 = r % (NTOK * NTOK);
        int p = r2 / NTOK, q = r2 % NTOK;
        int ip = p / 7, jp = p % 7, iq = q / 7, jq = q % 7;
        int ridx = (jp - jq + 6) * 13 + (ip - iq + 6);
        g_cmb[((wm * HEADS + h) * NTOK + p) * 56 + q] =
            mask[wm * (NTOK * NTOK) + p * NTOK + q] + table[ridx * HEADS + h];
    }
}

__global__ __launch_bounds__(NTHREADS, 1)
void winattn_fused_kernel(const float* __restrict__ x,
                          const float* __restrict__ b_proj,
                          float* __restrict__ out)
{
    extern __shared__ unsigned smu[];

    unsigned* xsu  = smu;
    unsigned* attu = smu;
    unsigned* qsu  = smu + OFF_QS;
    unsigned* ksu  = smu + OFF_KS;
    unsigned* vtu  = smu + OFF_VT;

    const unsigned sbase = (unsigned)__cvta_generic_to_shared(smu);

    const int tid  = threadIdx.x;
    const int lane = tid & 31;
    const int w    = tid >> 5;
    const int lg   = lane >> 2;
    const int lr   = lane & 3;
    const int lrow = (lane & 7) + ((lane >> 3) & 1) * 8;   // A-ldsm row
    const int lcol = (lane >> 4) * 4;                      // A-ldsm col
    const int brow8 = lane & 7;                            // B-ldsm row-within-tile
    const int bcol  = ((lane >> 3) & 1) * 4;               // B-ldsm col (0 or 4)
    const int btsel = lane >> 4;                           // B-ldsm tile select

    {
        const float4* xg4 = (const float4*)(x + (size_t)blockIdx.x * WPC * (NTOK * DIMC));
        #pragma unroll
        for (int j = 0; j < 5; j++) {
            int idx = tid + j * NTHREADS;
            if (idx < 2352) {
                float4 v = xg4[idx];
                int row = idx / 48, c4 = idx % 48;
                *(uint4*)&xsu[row * XS_STRIDE + c4 * 4] =
                    make_uint4(cvt_tf32(v.x), cvt_tf32(v.y), cvt_tf32(v.z), cvt_tf32(v.w));
            }
        }
        for (int i = tid; i < DIMC * 7; i += NTHREADS)
            vtu[(i / 7) * VT_STRIDE + 49 + (i % 7)] = 0u;   // pad persists all windows
    }
    __syncthreads();

    for (int it = 0; it < WPC; ++it) {
        const int b = blockIdx.x * WPC + it;

        // ====== phase 1: qkv = x @ w_qkv + b (TF32 MMA, B from L2) ======
        {
            const int ns = w >> 1;
            const int m0 = (w & 1) * 32;
            const uint2* gw = g_wfrag1 + ns * 6912 + lane;

            float d[2][9][4];
            #pragma unroll
            for (int s = 0; s < 2; s++)
                #pragma unroll
                for (int t = 0; t < 9; t++)
                    #pragma unroll
                    for (int j = 0; j < 4; j++) d[s][t][j] = 0.0f;

            const unsigned abase = sbase + (((m0 + lrow) * XS_STRIDE + lcol) << 2);
            #pragma unroll 4
            for (int k8 = 0; k8 < 24; ++k8) {
                uint2 bbv[9];
                #pragma unroll
                for (int t = 0; t < 9; t++) bbv[t] = gw[(k8 * 9 + t) * 32];

                unsigned a[2][4];
                ldsm4(a[0], abase + (k8 * 8 << 2));
                ldsm4(a[1], abase + ((16 * XS_STRIDE + k8 * 8) << 2));
                #pragma unroll
                for (int t = 0; t < 9; t++) {
                    mma_tf32(d[0][t], a[0], (const unsigned*)&bbv[t]);
                    mma_tf32(d[1][t], a[1], (const unsigned*)&bbv[t]);
                }
            }
            #pragma unroll
            for (int s = 0; s < 2; s++) {
                int r0 = m0 + s * 16 + lg, r1 = r0 + 8;
                #pragma unroll
                for (int t = 0; t < 9; t++) {
                    int col  = ns * 72 + t * 8 + 2 * lr;
                    int part = col / DIMC;
                    int cc   = col % DIMC;
                    float2 bq = *(const float2*)&g_bq[col];
                    if (part == 0) {
                        if (r0 < NTOK)
                            *(uint2*)&qsu[r0 * QKV_STRIDE + cc] =
                                make_uint2(cvt_tf32(d[s][t][0] + bq.x),
                                           cvt_tf32(d[s][t][1] + bq.y));
                        if (r1 < NTOK)
                            *(uint2*)&qsu[r1 * QKV_STRIDE + cc] =
                                make_uint2(cvt_tf32(d[s][t][2] + bq.x),
                                           cvt_tf32(d[s][t][3] + bq.y));
                    } else if (part == 1) {
                        if (r0 < NTOK)
                            *(uint2*)&ksu[r0 * QKV_STRIDE + cc] =
                                make_uint2(cvt_tf32(d[s][t][0] + bq.x),
                                           cvt_tf32(d[s][t][1] + bq.y));
                        if (r1 < NTOK)
                            *(uint2*)&ksu[r1 * QKV_STRIDE + cc] =
                                make_uint2(cvt_tf32(d[s][t][2] + bq.x),
                                           cvt_tf32(d[s][t][3] + bq.y));
                    } else {
                        if (r0 < NTOK) {
                            vtu[cc * VT_STRIDE + r0]       = cvt_tf32(d[s][t][0] + bq.x);
                            vtu[(cc + 1) * VT_STRIDE + r0] = cvt_tf32(d[s][t][1] + bq.y);
                        }
                        if (r1 < NTOK) {
                            vtu[cc * VT_STRIDE + r1]       = cvt_tf32(d[s][t][2] + bq.x);
                            vtu[(cc + 1) * VT_STRIDE + r1] = cvt_tf32(d[s][t][3] + bq.y);
                        }
                    }
                }
            }
        }
        __syncthreads();

        // ====== phase 2: attention — 24 (head, m16-tile) units over 16 warps ======
        {
            const int wm = b & (NWMASK - 1);
            for (int ui = w; ui < 24; ui += 16) {
                const int h  = ui >> 2;
                const int m0 = (ui & 3) * 16;

                // prefetch combined bias+mask rows (hides L2 under 2a MMAs)
                float2 cmb[2][7];
                #pragma unroll
                for (int half = 0; half < 2; half++) {
                    int p = m0 + lg + 8 * half;
                    int pc = (p < NTOK) ? p : (NTOK - 1);
                    const float2* crow =
                        (const float2*)&g_cmb[((wm * HEADS + h) * NTOK + pc) * 56];
                    #pragma unroll
                    for (int t = 0; t < 7; t++)
                        cmb[half][t] = crow[(t * 8 + 2 * lr) >> 1];
                }

                // 2a: S-tile = q k^T, B-fragments via ldmatrix over n-major K
                float d[7][4];
                #pragma unroll
                for (int t = 0; t < 7; t++)
                    #pragma unroll
                    for (int j = 0; j < 4; j++) d[t][j] = 0.0f;

                const unsigned qab = sbase +
                    ((OFF_QS + (m0 + lrow) * QKV_STRIDE + h * HDIM + lcol) << 2);
                const unsigned kB0 = sbase +
                    ((OFF_KS + (btsel * 8 + brow8) * QKV_STRIDE + h * HDIM + bcol) << 2);
                #pragma unroll
                for (int k8 = 0; k8 < 4; ++k8) {
                    unsigned a[4];
                    ldsm4(a, qab + (k8 * 8 << 2));
                    unsigned bb[14];
                    ldsm4(bb,      kB0 + ((0 * 8 * QKV_STRIDE + k8 * 8) << 2));
                    ldsm4(bb + 4,  kB0 + ((2 * 8 * QKV_STRIDE + k8 * 8) << 2));
                    ldsm4(bb + 8,  kB0 + ((4 * 8 * QKV_STRIDE + k8 * 8) << 2));
                    ldsm2(bb + 12, kB0 + ((6 * 8 * QKV_STRIDE + k8 * 8) << 2));
                    #pragma unroll
                    for (int t = 0; t < 7; t++)
                        mma_tf32(d[t], a, bb + 2 * t);
                }

                // softmax: zero-load, deferred normalization
                float inv2[2];
                #pragma unroll
                for (int half = 0; half < 2; half++) {
                    int p = m0 + lg + 8 * half;
                    float mx = -1e30f;
                    if (p < NTOK) {
                        #pragma unroll
                        for (int t = 0; t < 7; t++) {
                            int q0 = t * 8 + 2 * lr;
                            float v0 = -1e30f, v1 = -1e30f;
                            if (q0 < NTOK)     v0 = d[t][2 * half]     + cmb[half][t].x;
                            if (q0 + 1 < NTOK) v1 = d[t][2 * half + 1] + cmb[half][t].y;
                            d[t][2 * half]     = v0;
                            d[t][2 * half + 1] = v1;
                            mx = fmaxf(mx, fmaxf(v0, v1));
                        }
                    }
                    mx = fmaxf(mx, __shfl_xor_sync(0xffffffffu, mx, 1));
                    mx = fmaxf(mx, __shfl_xor_sync(0xffffffffu, mx, 2));
                    float sum = 0.0f;
                    if (p < NTOK) {
                        #pragma unroll
                        for (int t = 0; t < 7; t++) {
                            #pragma unroll
                            for (int c = 0; c < 2; c++) {
                                int q = t * 8 + 2 * lr + c;
                                float e = (q < NTOK) ? __expf(d[t][2 * half + c] - mx) : 0.0f;
                                d[t][2 * half + c] = e;
                                sum += e;
                            }
                        }
                        unsigned* arow = attu + (h * NTOK + p) * ATT_STRIDE;
                        #pragma unroll
                        for (int t = 0; t < 7; t++) {
                            int q0 = t * 8 + 2 * lr;
                            uint2 bits = make_uint2(0u, 0u);
                            if (q0 < NTOK)     bits.x = cvt_tf32(d[t][2 * half]);
                            if (q0 + 1 < NTOK) bits.y = cvt_tf32(d[t][2 * half + 1]);
                            *(uint2*)&arow[q0] = bits;
                        }
                    }
                    sum += __shfl_xor_sync(0xffffffffu, sum, 1);
                    sum += __shfl_xor_sync(0xffffffffu, sum, 2);
                    inv2[half] = 1.0f / sum;
                }
                __syncwarp();

                // 2c: O-tile = E @ V, B-fragments via ldmatrix over n-major V^T
                float o[4][4];
                #pragma unroll
                for (int t = 0; t < 4; t++)
                    #pragma unroll
                    for (int j = 0; j < 4; j++) o[t][j] = 0.0f;

                const unsigned aab = sbase +
                    (((h * NTOK + m0 + lrow) * ATT_STRIDE + lcol) << 2);
                const unsigned vB0 = sbase +
                    ((OFF_VT + (h * HDIM + btsel * 8 + brow8) * VT_STRIDE + bcol) << 2);
                #pragma unroll
                for (int k8 = 0; k8 < 7; ++k8) {
                    unsigned a[4];
                    ldsm4(a, aab + (k8 * 8 << 2));
                    unsigned bb[8];
                    ldsm4(bb,     vB0 + ((0 * 8 * VT_STRIDE + k8 * 8) << 2));
                    ldsm4(bb + 4, vB0 + ((2 * 8 * VT_STRIDE + k8 * 8) << 2));
                    #pragma unroll
                    for (int t = 0; t < 4; t++)
                        mma_tf32(o[t], a, bb + 2 * t);
                }
                int r0 = m0 + lg, r1 = r0 + 8;
                #pragma unroll
                for (int t = 0; t < 4; t++) {
                    int dc = h * HDIM + t * 8 + 2 * lr;
                    if (r0 < NTOK)
                        *(uint2*)&qsu[r0 * QKV_STRIDE + dc] =
                            make_uint2(cvt_tf32(o[t][0] * inv2[0]),
                                       cvt_tf32(o[t][1] * inv2[0]));
                    if (r1 < NTOK)
                        *(uint2*)&qsu[r1 * QKV_STRIDE + dc] =
                            make_uint2(cvt_tf32(o[t][2] * inv2[1]),
                                       cvt_tf32(o[t][3] * inv2[1]));
                }
            }
        }
        __syncthreads();

        const bool havex = (it + 1 < WPC);
        float4 xpre[5];
        if (havex) {
            const float4* xg4 = (const float4*)(x + (size_t)(b + 1) * (NTOK * DIMC));
            #pragma unroll
            for (int j = 0; j < 5; j++) {
                int idx = tid + j * NTHREADS;
                if (idx < 2352) xpre[j] = xg4[idx];
            }
        }

        // ====== phase 3: out = O @ w_proj + b_proj (TF32 MMA, B from L2) ======
        {
            const int ns = w >> 1;
            const int m0 = (w & 1) * 32;
            const uint2* gw = g_wfrag3 + ns * 2304 + lane;

            float d[2][3][4];
            #pragma unroll
            for (int s = 0; s < 2; s++)
                #pragma unroll
                for (int t = 0; t < 3; t++)
                    #pragma unroll
                    for (int j = 0; j < 4; j++) d[s][t][j] = 0.0f;

            const unsigned oab = sbase +
                ((OFF_QS + (m0 + lrow) * QKV_STRIDE + lcol) << 2);
            #pragma unroll 4
            for (int k8 = 0; k8 < 24; ++k8) {
                uint2 bbv[3];
                #pragma unroll
                for (int t = 0; t < 3; t++) bbv[t] = gw[(k8 * 3 + t) * 32];

                unsigned a[2][4];
                ldsm4(a[0], oab + (k8 * 8 << 2));
                ldsm4(a[1], oab + ((16 * QKV_STRIDE + k8 * 8) << 2));
                #pragma unroll
                for (int t = 0; t < 3; t++) {
                    mma_tf32(d[0][t], a[0], (const unsigned*)&bbv[t]);
                    mma_tf32(d[1][t], a[1], (const unsigned*)&bbv[t]);
                }
            }
            float* og = out + (size_t)b * (NTOK * DIMC);
            #pragma unroll
            for (int s = 0; s < 2; s++) {
                int r0 = m0 + s * 16 + lg, r1 = r0 + 8;
                #pragma unroll
                for (int t = 0; t < 3; t++) {
                    int col = ns * 24 + t * 8 + 2 * lr;
                    float2 bv = *(const float2*)&b_proj[col];
                    if (r0 < NTOK)
                        *(float2*)&og[r0 * DIMC + col] =
                            make_float2(d[s][t][0] + bv.x, d[s][t][1] + bv.y);
                    if (r1 < NTOK)
                        *(float2*)&og[r1 * DIMC + col] =
                            make_float2(d[s][t][2] + bv.x, d[s][t][3] + bv.y);
                }
            }
        }

        if (havex) {
            #pragma unroll
            for (int j = 0; j < 5; j++) {
                int idx = tid + j * NTHREADS;
                if (idx < 2352) {
                    int row = idx / 48, c4 = idx % 48;
                    *(uint4*)&xsu[row * XS_STRIDE + c4 * 4] =
                        make_uint4(cvt_tf32(xpre[j].x), cvt_tf32(xpre[j].y),
                                   cvt_tf32(xpre[j].z), cvt_tf32(xpre[j].w));
                }
            }
        }
        __syncthreads();
    }
}

extern "C" void kernel_launch(void* const* d_in, const int* in_sizes, int n_in,
                              void* d_out, int out_size)
{
    const float* x      = (const float*)d_in[0];
    const float* mask   = (const float*)d_in[1];
    const float* w_qkv  = (const float*)d_in[2];
    const float* b_qkv  = (const float*)d_in[3];
    const float* w_proj = (const float*)d_in[4];
    const float* b_proj = (const float*)d_in[5];
    const float* table  = (const float*)d_in[6];
    float* out = (float*)d_out;

    prep_kernel<<<148, 256>>>(w_qkv, w_proj, table, mask, b_qkv);

    const int smem_bytes = SMEM_WORDS * (int)sizeof(unsigned);
    cudaFuncSetAttribute(winattn_fused_kernel,
                         cudaFuncAttributeMaxDynamicSharedMemorySize, smem_bytes);

    winattn_fused_kernel<<<NCTAS, NTHREADS, smem_bytes>>>(x, b_proj, out);
}